// round 6
// baseline (speedup 1.0000x reference)
#include <cuda_runtime.h>
#include <cuda_bf16.h>
#include <math.h>

// Problem constants
#define D_MODEL 768
#define N_HEADS 12
#define DH 64
#define BATCH 8
#define SEQ 256
#define NLAYER 6
#define MROWS (BATCH * SEQ)          // 2048
#define DFF (4 * D_MODEL)            // 3072
#define MD ((size_t)MROWS * D_MODEL) // 2048*768

// GEMM tile config
#define BM 128
#define BN 128
#define BK 16

// ---------------- scratch (device globals; no runtime allocation) ----------------
__device__ float g_x[MROWS * D_MODEL];
__device__ float g_y[MROWS * D_MODEL];
__device__ float g_qkv[3 * MROWS * D_MODEL];
__device__ float g_tmp[MROWS * D_MODEL];     // attention out / ffn2 out
__device__ float g_ffn[MROWS * DFF];         // ffn hidden

// ---------------- helpers ----------------
__device__ __forceinline__ float gelu_exact(float x) {
    return 0.5f * x * (1.0f + erff(x * 0.70710678118654752f));
}

__device__ __forceinline__ void cp_async16(void* smem, const void* gmem) {
    unsigned saddr = (unsigned)__cvta_generic_to_shared(smem);
    asm volatile("cp.async.cg.shared.global [%0], [%1], 16;\n" :: "r"(saddr), "l"(gmem));
}
__device__ __forceinline__ void cp_commit() {
    asm volatile("cp.async.commit_group;\n" ::: "memory");
}
__device__ __forceinline__ void cp_wait1() {
    asm volatile("cp.async.wait_group 1;\n" ::: "memory");
}
__device__ __forceinline__ void cp_wait0() {
    asm volatile("cp.async.wait_group 0;\n" ::: "memory");
}

__device__ __forceinline__ unsigned long long pack_dup(float a) {
    unsigned long long r;
    asm("mov.b64 %0, {%1, %1};" : "=l"(r) : "f"(a));
    return r;
}
__device__ __forceinline__ void fma2(unsigned long long& c, unsigned long long a, unsigned long long b) {
    asm("fma.rn.f32x2 %0, %1, %2, %0;" : "+l"(c) : "l"(a), "l"(b));
}
__device__ __forceinline__ float2 unpack_f2(unsigned long long v) {
    float2 r;
    asm("mov.b64 {%0, %1}, %2;" : "=f"(r.x), "=f"(r.y) : "l"(v));
    return r;
}

// ---------------- SGEMM v2: C[z] = act(A @ W[z] + bias[z]) ----------------
// 128x128 block, BK=16, 256 threads, 8x8 per thread via packed f32x2 FMA.
// Double-buffered cp.async. A0 used for z==0, A1 for z>0 (fused QKV with
// cross-attention q-source split).
template<int ACT>
__global__ __launch_bounds__(256) void sgemm_kernel(
    const float* __restrict__ A0, const float* __restrict__ A1,
    const float* __restrict__ W, const float* __restrict__ bias,
    float* __restrict__ C, int N, int K,
    int wStrideZ, int biasStrideZ, size_t cStrideZ)
{
    const int z = blockIdx.z;
    const float* __restrict__ A = (z == 0) ? A0 : A1;
    W += (size_t)z * wStrideZ;
    bias += (size_t)z * biasStrideZ;
    C += (size_t)z * cStrideZ;

    __shared__ float As[2][BM][BK];   // [m][k]
    __shared__ float Bs[2][BK][BN];   // [k][n]

    const int t  = threadIdx.x;
    const int tx = t & 15;            // n group: cols tx*4..+3 and 64+tx*4..+3
    const int ty = t >> 4;            // m group: rows ty*4..+3 and 64+ty*4..+3
    const int rowBase = blockIdx.y * BM;
    const int colBase = blockIdx.x * BN;

    // load indices
    const int aRow  = t >> 2;         // 0..63 (and +64)
    const int aCol4 = (t & 3) * 4;    // 0,4,8,12
    const int bRow  = t >> 5;         // 0..7 (and +8)
    const int bCol4 = (t & 31) * 4;   // 0..124

    const float* Ag = A + (size_t)rowBase * K;
    const float* Wg = W + colBase;

    unsigned long long acc[8][4];
#pragma unroll
    for (int i = 0; i < 8; i++)
#pragma unroll
        for (int j = 0; j < 4; j++) acc[i][j] = 0ULL;

    // prologue: load tile 0
    {
        cp_async16(&As[0][aRow][aCol4],      Ag + (size_t)aRow * K + aCol4);
        cp_async16(&As[0][aRow + 64][aCol4], Ag + (size_t)(aRow + 64) * K + aCol4);
        cp_async16(&Bs[0][bRow][bCol4],      Wg + (size_t)bRow * N + bCol4);
        cp_async16(&Bs[0][bRow + 8][bCol4],  Wg + (size_t)(bRow + 8) * N + bCol4);
        cp_commit();
    }

    int buf = 0;
    for (int kt = 0; kt < K; kt += BK) {
        const bool hasNext = (kt + BK) < K;
        if (hasNext) {
            const int nb = buf ^ 1;
            const int kn = kt + BK;
            cp_async16(&As[nb][aRow][aCol4],      Ag + (size_t)aRow * K + kn + aCol4);
            cp_async16(&As[nb][aRow + 64][aCol4], Ag + (size_t)(aRow + 64) * K + kn + aCol4);
            cp_async16(&Bs[nb][bRow][bCol4],      Wg + (size_t)(kn + bRow) * N + bCol4);
            cp_async16(&Bs[nb][bRow + 8][bCol4],  Wg + (size_t)(kn + bRow + 8) * N + bCol4);
            cp_commit();
            cp_wait1();
        } else {
            cp_wait0();
        }
        __syncthreads();

#pragma unroll
        for (int k = 0; k < BK; k++) {
            float a[8];
#pragma unroll
            for (int i = 0; i < 4; i++) {
                a[i]     = As[buf][ty * 4 + i][k];
                a[i + 4] = As[buf][64 + ty * 4 + i][k];
            }
            unsigned long long bp0 = *(const unsigned long long*)&Bs[buf][k][tx * 4];
            unsigned long long bp1 = *(const unsigned long long*)&Bs[buf][k][tx * 4 + 2];
            unsigned long long bp2 = *(const unsigned long long*)&Bs[buf][k][64 + tx * 4];
            unsigned long long bp3 = *(const unsigned long long*)&Bs[buf][k][64 + tx * 4 + 2];
#pragma unroll
            for (int i = 0; i < 8; i++) {
                unsigned long long aa = pack_dup(a[i]);
                fma2(acc[i][0], aa, bp0);
                fma2(acc[i][1], aa, bp1);
                fma2(acc[i][2], aa, bp2);
                fma2(acc[i][3], aa, bp3);
            }
        }
        __syncthreads();
        buf ^= 1;
    }

    // epilogue: bias + optional GELU, write 8 rows x (two float4)
    float4 bb0 = *(const float4*)(bias + colBase + tx * 4);
    float4 bb1 = *(const float4*)(bias + colBase + 64 + tx * 4);
#pragma unroll
    for (int i = 0; i < 8; i++) {
        int row = rowBase + ((i < 4) ? (ty * 4 + i) : (64 + ty * 4 + (i - 4)));
        float2 c0 = unpack_f2(acc[i][0]);
        float2 c1 = unpack_f2(acc[i][1]);
        float2 c2 = unpack_f2(acc[i][2]);
        float2 c3 = unpack_f2(acc[i][3]);
        float4 o0, o1;
        o0.x = c0.x + bb0.x; o0.y = c0.y + bb0.y; o0.z = c1.x + bb0.z; o0.w = c1.y + bb0.w;
        o1.x = c2.x + bb1.x; o1.y = c2.y + bb1.y; o1.z = c3.x + bb1.z; o1.w = c3.y + bb1.w;
        if (ACT == 1) {
            o0.x = gelu_exact(o0.x); o0.y = gelu_exact(o0.y);
            o0.z = gelu_exact(o0.z); o0.w = gelu_exact(o0.w);
            o1.x = gelu_exact(o1.x); o1.y = gelu_exact(o1.y);
            o1.z = gelu_exact(o1.z); o1.w = gelu_exact(o1.w);
        }
        *(float4*)(C + (size_t)row * N + colBase + tx * 4)      = o0;
        *(float4*)(C + (size_t)row * N + colBase + 64 + tx * 4) = o1;
    }
}

// ---------------- fused attention (softmax(QK^T*scale + maskbias) @ V) ----------------
// grid (B*H, 4): each block handles 64 query rows with 64 threads (1 q/thread).
// K/V streamed through 64-row smem chunks; online softmax.
__global__ __launch_bounds__(64) void attn_kernel(
    const float* __restrict__ qb, const float* __restrict__ kb,
    const float* __restrict__ vb, const int* __restrict__ mask,
    float* __restrict__ out)
{
    const int bh = blockIdx.x;
    const int b = bh / N_HEADS;
    const int h = bh % N_HEADS;
    const int t = threadIdx.x;
    const int q = blockIdx.y * 64 + t;

    __shared__ float Ks[64 * 64];
    __shared__ float Vs[64 * 64];
    __shared__ float mb[SEQ];

#pragma unroll
    for (int j = 0; j < 4; j++) {
        int i = t + j * 64;
        mb[i] = -10000.0f * (1.0f - (float)mask[b * SEQ + i]);
    }

    const size_t qoff = ((size_t)(b * SEQ + q)) * D_MODEL + h * DH;
    float4 q4[16];
    const float4* qp = (const float4*)(qb + qoff);
#pragma unroll
    for (int i = 0; i < 16; i++) q4[i] = qp[i];

    float4 acc[16];
#pragma unroll
    for (int i = 0; i < 16; i++) acc[i] = make_float4(0.f, 0.f, 0.f, 0.f);
    float m = -1e30f, l = 0.0f;

    for (int kc = 0; kc < 4; kc++) {
        __syncthreads();
#pragma unroll
        for (int it = 0; it < 16; it++) {
            int idx = t + it * 64;             // float4 index 0..1023
            int r = idx >> 4;
            int c = idx & 15;
            size_t gof = ((size_t)(b * SEQ + kc * 64 + r)) * D_MODEL + h * DH + c * 4;
            ((float4*)Ks)[idx] = *(const float4*)(kb + gof);
            ((float4*)Vs)[idx] = *(const float4*)(vb + gof);
        }
        __syncthreads();

        for (int kk = 0; kk < 64; kk++) {
            const float4* Kr = (const float4*)(Ks + kk * 64);
            float dot = 0.0f;
#pragma unroll
            for (int i = 0; i < 16; i++) {
                dot += q4[i].x * Kr[i].x + q4[i].y * Kr[i].y
                     + q4[i].z * Kr[i].z + q4[i].w * Kr[i].w;
            }
            float s  = dot * 0.125f + mb[kc * 64 + kk];
            float nm = fmaxf(m, s);
            float corr = __expf(m - nm);
            float p    = __expf(s - nm);
            l = l * corr + p;
            const float4* Vr = (const float4*)(Vs + kk * 64);
#pragma unroll
            for (int i = 0; i < 16; i++) {
                acc[i].x = fmaf(acc[i].x, corr, p * Vr[i].x);
                acc[i].y = fmaf(acc[i].y, corr, p * Vr[i].y);
                acc[i].z = fmaf(acc[i].z, corr, p * Vr[i].z);
                acc[i].w = fmaf(acc[i].w, corr, p * Vr[i].w);
            }
            m = nm;
        }
    }

    float inv = 1.0f / l;
    float4* op = (float4*)(out + qoff);
#pragma unroll
    for (int i = 0; i < 16; i++)
        op[i] = make_float4(acc[i].x * inv, acc[i].y * inv, acc[i].z * inv, acc[i].w * inv);
}

// ---------------- residual add + LayerNorm (in-place into x) ----------------
__global__ __launch_bounds__(256) void add_ln_kernel(
    float* __restrict__ x, const float* __restrict__ r,
    const float* __restrict__ g, const float* __restrict__ b)
{
    const int row = blockIdx.x;
    const int t = threadIdx.x;
    const size_t base = (size_t)row * D_MODEL;

    float v[3];
    float s = 0.f, s2 = 0.f;
#pragma unroll
    for (int j = 0; j < 3; j++) {
        int i = t + j * 256;
        float val = x[base + i] + r[base + i];
        v[j] = val;
        s += val;
        s2 += val * val;
    }
    __shared__ float sh1[256], sh2[256];
    sh1[t] = s; sh2[t] = s2;
    __syncthreads();
    for (int o = 128; o > 0; o >>= 1) {
        if (t < o) { sh1[t] += sh1[t + o]; sh2[t] += sh2[t + o]; }
        __syncthreads();
    }
    float mean = sh1[0] * (1.0f / D_MODEL);
    float var  = sh2[0] * (1.0f / D_MODEL) - mean * mean;
    float rstd = rsqrtf(var + 1e-12f);
#pragma unroll
    for (int j = 0; j < 3; j++) {
        int i = t + j * 256;
        x[base + i] = (v[j] - mean) * rstd * g[i] + b[i];
    }
}

// ---------------- host orchestration ----------------
extern "C" void kernel_launch(void* const* d_in, const int* in_sizes, int n_in,
                              void* d_out, int out_size)
{
    (void)in_sizes; (void)n_in;
    const float* in_x    = (const float*)d_in[0];
    const float* in_y    = (const float*)d_in[1];
    const int*   x_mask  = (const int*)d_in[2];
    const int*   y_mask  = (const int*)d_in[3];
    const float* ax_w = (const float*)d_in[4];
    const float* ax_b = (const float*)d_in[5];
    const float* cx_w = (const float*)d_in[6];
    const float* cx_b = (const float*)d_in[7];
    const float* fx_w1 = (const float*)d_in[8];
    const float* fx_b1 = (const float*)d_in[9];
    const float* fx_w2 = (const float*)d_in[10];
    const float* fx_b2 = (const float*)d_in[11];
    const float* ay_w = (const float*)d_in[12];
    const float* ay_b = (const float*)d_in[13];
    const float* cy_w = (const float*)d_in[14];
    const float* cy_b = (const float*)d_in[15];
    const float* fy_w1 = (const float*)d_in[16];
    const float* fy_b1 = (const float*)d_in[17];
    const float* fy_w2 = (const float*)d_in[18];
    const float* fy_b2 = (const float*)d_in[19];
    const float* lnx_g = (const float*)d_in[20];
    const float* lnx_b = (const float*)d_in[21];
    const float* lny_g = (const float*)d_in[22];
    const float* lny_b = (const float*)d_in[23];
    float* out = (float*)d_out;
    (void)out_size;

    float *gx, *gy, *gqkv, *gtmp, *gffn;
    cudaGetSymbolAddress((void**)&gx,   g_x);
    cudaGetSymbolAddress((void**)&gy,   g_y);
    cudaGetSymbolAddress((void**)&gqkv, g_qkv);
    cudaGetSymbolAddress((void**)&gtmp, g_tmp);
    cudaGetSymbolAddress((void**)&gffn, g_ffn);

    cudaMemcpyAsync(gx, in_x, MD * sizeof(float), cudaMemcpyDeviceToDevice, 0);
    cudaMemcpyAsync(gy, in_y, MD * sizeof(float), cudaMemcpyDeviceToDevice, 0);

    const dim3 gridProj(D_MODEL / BN, MROWS / BM, 3);   // fused QKV: 6x16x3
    const dim3 gridF1(DFF / BN, MROWS / BM, 1);         // 24x16
    const dim3 gridF2(D_MODEL / BN, MROWS / BM, 1);     // 6x16
    const dim3 gridAttn(BATCH * N_HEADS, 4, 1);         // 384 blocks
    const int DD = D_MODEL * D_MODEL;

    // one attention sublayer: cur = LN(cur + attn(q=cur, kv=kvsrc))
    auto attn_block = [&](float* cur, const float* kvsrc,
                          const float* w, const float* bb,
                          const int* mask, const float* lg, const float* lb) {
        sgemm_kernel<0><<<gridProj, 256>>>(cur, kvsrc, w, bb, gqkv,
                                           D_MODEL, D_MODEL, DD, D_MODEL, MD);
        attn_kernel<<<gridAttn, 64>>>(gqkv, gqkv + MD, gqkv + 2 * MD, mask, gtmp);
        add_ln_kernel<<<MROWS, 256>>>(cur, gtmp, lg, lb);
    };
    // one FFN sublayer: cur = LN(cur + W2(gelu(W1 cur + b1)) + b2)
    auto ffn_block = [&](float* cur, const float* w1, const float* b1,
                         const float* w2, const float* b2,
                         const float* lg, const float* lb) {
        sgemm_kernel<1><<<gridF1, 256>>>(cur, cur, w1, b1, gffn,
                                         DFF, D_MODEL, 0, 0, 0);
        sgemm_kernel<0><<<gridF2, 256>>>(gffn, gffn, w2, b2, gtmp,
                                         D_MODEL, DFF, 0, 0, 0);
        add_ln_kernel<<<MROWS, 256>>>(cur, gtmp, lg, lb);
    };

    for (int L = 0; L < NLAYER; L++) {
        const size_t wOff = (size_t)L * 3 * DD;
        const size_t bOff = (size_t)L * 3 * D_MODEL;
        // 1) x self-attention
        attn_block(gx, gx, ax_w + wOff, ax_b + bOff, x_mask, lnx_g + 0 * D_MODEL, lnx_b + 0 * D_MODEL);
        // 2) y self-attention
        attn_block(gy, gy, ay_w + wOff, ay_b + bOff, y_mask, lny_g + 0 * D_MODEL, lny_b + 0 * D_MODEL);
        // 3) x cross-attention (q from x, kv from updated y)
        attn_block(gx, gy, cx_w + wOff, cx_b + bOff, y_mask, lnx_g + 1 * D_MODEL, lnx_b + 1 * D_MODEL);
        // 4) y cross-attention (q from y, kv from updated x)
        attn_block(gy, gx, cy_w + wOff, cy_b + bOff, x_mask, lny_g + 1 * D_MODEL, lny_b + 1 * D_MODEL);
        // 5) x FFN
        ffn_block(gx, fx_w1 + (size_t)L * D_MODEL * DFF, fx_b1 + (size_t)L * DFF,
                      fx_w2 + (size_t)L * DFF * D_MODEL, fx_b2 + (size_t)L * D_MODEL,
                      lnx_g + 2 * D_MODEL, lnx_b + 2 * D_MODEL);
        // 6) y FFN
        ffn_block(gy, fy_w1 + (size_t)L * D_MODEL * DFF, fy_b1 + (size_t)L * DFF,
                      fy_w2 + (size_t)L * DFF * D_MODEL, fy_b2 + (size_t)L * D_MODEL,
                      lny_g + 2 * D_MODEL, lny_b + 2 * D_MODEL);
    }

    cudaMemcpyAsync(out,      gx, MD * sizeof(float), cudaMemcpyDeviceToDevice, 0);
    cudaMemcpyAsync(out + MD, gy, MD * sizeof(float), cudaMemcpyDeviceToDevice, 0);
}

// round 10
// speedup vs baseline: 1.5892x; 1.5892x over previous
#include <cuda_runtime.h>
#include <cuda_bf16.h>
#include <math.h>
#include <stdint.h>

// ---------------- problem constants ----------------
#define D_MODEL 768
#define N_HEADS 12
#define DH 64
#define BATCH 8
#define SEQ 256
#define NLAYER 6
#define MROWS 2048
#define DFF 3072
#define MD ((size_t)MROWS * D_MODEL)
#define DDW (D_MODEL * D_MODEL)           // 589824

// converted-weight scratch offsets (elements)
#define OFF_AX   0
#define OFF_CX   10616832                  // 18 * 589824
#define OFF_AY   21233664
#define OFF_CY   31850496
#define OFF_FXW1 42467328
#define OFF_FYW1 56623104
#define OFF_FXW2 70778880
#define OFF_FYW2 84934656
#define WELEMS   99090432

// ---------------- scratch (device globals; no runtime allocation) ----------------
__device__ float g_x[MROWS * D_MODEL];
__device__ float g_y[MROWS * D_MODEL];
__device__ float g_qkv[3 * MROWS * D_MODEL];
__device__ float g_tmp[MROWS * D_MODEL];
__device__ __nv_bfloat16 g_xh[MROWS * D_MODEL];
__device__ __nv_bfloat16 g_xl[MROWS * D_MODEL];
__device__ __nv_bfloat16 g_yh[MROWS * D_MODEL];
__device__ __nv_bfloat16 g_yl[MROWS * D_MODEL];
__device__ __nv_bfloat16 g_hh[MROWS * DFF];
__device__ __nv_bfloat16 g_hl[MROWS * DFF];
__device__ __nv_bfloat16 g_wth[WELEMS];
__device__ __nv_bfloat16 g_wtl[WELEMS];

// ---------------- helpers ----------------
__device__ __forceinline__ void cp_async16(void* smemp, const void* gmem) {
    unsigned saddr = (unsigned)__cvta_generic_to_shared(smemp);
    asm volatile("cp.async.cg.shared.global [%0], [%1], 16;\n" :: "r"(saddr), "l"(gmem));
}
__device__ __forceinline__ void cp_commit() {
    asm volatile("cp.async.commit_group;\n" ::: "memory");
}
__device__ __forceinline__ void cp_wait1() {
    asm volatile("cp.async.wait_group 1;\n" ::: "memory");
}
__device__ __forceinline__ void cp_wait0() {
    asm volatile("cp.async.wait_group 0;\n" ::: "memory");
}
__device__ __forceinline__ uint32_t ld32(const void* p) {
    return *(const uint32_t*)p;
}
__device__ __forceinline__ void mma_bf16(float* c, const uint32_t* a, uint32_t b0, uint32_t b1) {
    asm volatile(
        "mma.sync.aligned.m16n8k16.row.col.f32.bf16.bf16.f32 "
        "{%0,%1,%2,%3}, {%4,%5,%6,%7}, {%8,%9}, {%0,%1,%2,%3};"
        : "+f"(c[0]), "+f"(c[1]), "+f"(c[2]), "+f"(c[3])
        : "r"(a[0]), "r"(a[1]), "r"(a[2]), "r"(a[3]), "r"(b0), "r"(b1));
}
__device__ __forceinline__ float gelu_exact(float x) {
    return 0.5f * x * (1.0f + erff(x * 0.70710678118654752f));
}
__device__ __forceinline__ void split_bf16(float v, __nv_bfloat16& h, __nv_bfloat16& l) {
    h = __float2bfloat16(v);
    l = __float2bfloat16(v - __bfloat162float(h));
}

// ---------------- weight transpose + bf16 hi/lo split ----------------
// in: W [nMat][K][N] fp32 ; out: Wt_hi/lo [nMat][N][K] bf16
__global__ __launch_bounds__(256) void wconv_kernel(
    const float* __restrict__ src, __nv_bfloat16* __restrict__ dh,
    __nv_bfloat16* __restrict__ dl, int K, int N)
{
    __shared__ float tile[32][33];
    const int mat = blockIdx.z;
    const float* s = src + (size_t)mat * K * N;
    const size_t dbase = (size_t)mat * K * N;
    const int n0 = blockIdx.x * 32, k0 = blockIdx.y * 32;
    const int tx = threadIdx.x, ty = threadIdx.y;   // (32, 8)
#pragma unroll
    for (int j = 0; j < 4; j++)
        tile[ty + j * 8][tx] = s[(size_t)(k0 + ty + j * 8) * N + n0 + tx];
    __syncthreads();
#pragma unroll
    for (int j = 0; j < 4; j++) {
        int nl = ty + j * 8;
        float v = tile[tx][nl];
        __nv_bfloat16 h, l;
        split_bf16(v, h, l);
        size_t o = dbase + (size_t)(n0 + nl) * K + k0 + tx;
        dh[o] = h; dl[o] = l;
    }
}

// fp32 -> bf16 hi/lo (row-major passthrough)
__global__ __launch_bounds__(256) void aconv_kernel(
    const float* __restrict__ src, __nv_bfloat16* __restrict__ dh,
    __nv_bfloat16* __restrict__ dl, int n)
{
    int i = blockIdx.x * 256 + threadIdx.x;
    if (i < n) {
        __nv_bfloat16 h, l;
        split_bf16(src[i], h, l);
        dh[i] = h; dl[i] = l;
    }
}

// ---------------- bf16 split GEMM via mma.sync (HMMA) ----------------
// C[z] = act(A @ W[z]^T-stored + bias[z]); A=Ah+Al, W=Wh+Wl; 3 of 4 product terms.
// Tiles 128x128x32, 8 warps, warp tile 32x64. smem row stride 40 bf16 (80B):
// conflict-free fragment LDS + 16B-aligned cp.async rows.
#define TILE_B   10240                      // 128 * 40 * 2 bytes
#define BUF_B    (4 * TILE_B)               // Ah, Al, Bh, Bl
#define SMEM_BYTES (2 * BUF_B)              // 81920

template<int ACT, int OUTBF>
__global__ __launch_bounds__(256) void mma_gemm(
    const __nv_bfloat16* __restrict__ A0h, const __nv_bfloat16* __restrict__ A0l,
    const __nv_bfloat16* __restrict__ A1h, const __nv_bfloat16* __restrict__ A1l,
    const __nv_bfloat16* __restrict__ Bh,  const __nv_bfloat16* __restrict__ Bl,
    const float* __restrict__ bias,
    float* __restrict__ C, __nv_bfloat16* __restrict__ Ch, __nv_bfloat16* __restrict__ Cl,
    int N, int K, size_t wStrideZ, int biasStrideZ, size_t cStrideZ)
{
    extern __shared__ char smem[];
    const int z = blockIdx.z;
    const __nv_bfloat16* __restrict__ Ah = (z == 0) ? A0h : A1h;
    const __nv_bfloat16* __restrict__ Al = (z == 0) ? A0l : A1l;
    Bh += (size_t)z * wStrideZ;
    Bl += (size_t)z * wStrideZ;
    bias += (size_t)z * biasStrideZ;

    const int t = threadIdx.x;
    const int warp = t >> 5;
    const int lid  = t & 31;
    const int g  = lid >> 2;        // 0..7
    const int tg = lid & 3;         // 0..3
    const int warp_m = warp >> 1;   // 0..3  -> 32-row strip
    const int warp_n = warp & 1;    // 0..1  -> 64-col strip
    const int rowBase = blockIdx.y * 128;
    const int colBase = blockIdx.x * 128;

    const __nv_bfloat16* Agh = Ah + (size_t)rowBase * K;
    const __nv_bfloat16* Agl = Al + (size_t)rowBase * K;
    const __nv_bfloat16* Bgh = Bh + (size_t)colBase * K;
    const __nv_bfloat16* Bgl = Bl + (size_t)colBase * K;

    float c[2][8][4];
#pragma unroll
    for (int m = 0; m < 2; m++)
#pragma unroll
        for (int n = 0; n < 8; n++)
#pragma unroll
            for (int i = 0; i < 4; i++) c[m][n][i] = 0.0f;

    // loader: per tile 512 x 16B chunks, 2 per thread per tile
    auto load_chunk = [&](int buf, int kt) {
        char* base = smem + buf * BUF_B;
#pragma unroll
        for (int half = 0; half < 2; half++) {
            int idx = t + half * 256;       // 0..511
            int row = idx >> 2;
            int q   = idx & 3;
            size_t go = (size_t)row * K + kt + q * 8;
            uint32_t so = row * 80 + q * 16;
            cp_async16(base + so,                Agh + go);
            cp_async16(base + TILE_B + so,       Agl + go);
            cp_async16(base + 2 * TILE_B + so,   Bgh + go);
            cp_async16(base + 3 * TILE_B + so,   Bgl + go);
        }
        cp_commit();
    };

    auto compute_chunk = [&](int buf) {
        const char* base = smem + buf * BUF_B;
        const __nv_bfloat16* AsH = (const __nv_bfloat16*)(base);
        const __nv_bfloat16* AsL = (const __nv_bfloat16*)(base + TILE_B);
        const __nv_bfloat16* BsH = (const __nv_bfloat16*)(base + 2 * TILE_B);
        const __nv_bfloat16* BsL = (const __nv_bfloat16*)(base + 3 * TILE_B);
#pragma unroll
        for (int ks = 0; ks < 2; ks++) {
            const int k0 = ks * 16 + tg * 2;
            uint32_t ah[2][4], al[2][4];
#pragma unroll
            for (int m = 0; m < 2; m++) {
                int r0 = warp_m * 32 + m * 16 + g;
                ah[m][0] = ld32(AsH + r0 * 40 + k0);
                ah[m][1] = ld32(AsH + (r0 + 8) * 40 + k0);
                ah[m][2] = ld32(AsH + r0 * 40 + k0 + 8);
                ah[m][3] = ld32(AsH + (r0 + 8) * 40 + k0 + 8);
                al[m][0] = ld32(AsL + r0 * 40 + k0);
                al[m][1] = ld32(AsL + (r0 + 8) * 40 + k0);
                al[m][2] = ld32(AsL + r0 * 40 + k0 + 8);
                al[m][3] = ld32(AsL + (r0 + 8) * 40 + k0 + 8);
            }
#pragma unroll
            for (int n = 0; n < 8; n++) {
                int br = warp_n * 64 + n * 8 + g;
                uint32_t bh0 = ld32(BsH + br * 40 + k0);
                uint32_t bh1 = ld32(BsH + br * 40 + k0 + 8);
                uint32_t bl0 = ld32(BsL + br * 40 + k0);
                uint32_t bl1 = ld32(BsL + br * 40 + k0 + 8);
#pragma unroll
                for (int m = 0; m < 2; m++) {
                    mma_bf16(c[m][n], ah[m], bh0, bh1);   // Ah*Bh
                    mma_bf16(c[m][n], ah[m], bl0, bl1);   // Ah*Bl
                    mma_bf16(c[m][n], al[m], bh0, bh1);   // Al*Bh
                }
            }
        }
    };

    const int nc = K / 32;
    load_chunk(0, 0);
    for (int ck = 0; ck < nc; ck++) {
        if (ck + 1 < nc) {
            load_chunk((ck + 1) & 1, (ck + 1) * 32);
            cp_wait1();
        } else {
            cp_wait0();
        }
        __syncthreads();
        compute_chunk(ck & 1);
        __syncthreads();
    }

    // epilogue: bias (+GELU), store fp32 or bf16 hi/lo split
#pragma unroll
    for (int m = 0; m < 2; m++) {
        int r0 = rowBase + warp_m * 32 + m * 16 + g;
#pragma unroll
        for (int n = 0; n < 8; n++) {
            int col = colBase + warp_n * 64 + n * 8 + tg * 2;
            float2 bv = *(const float2*)(bias + col);
            float v0 = c[m][n][0] + bv.x;
            float v1 = c[m][n][1] + bv.y;
            float v2 = c[m][n][2] + bv.x;
            float v3 = c[m][n][3] + bv.y;
            if (ACT == 1) {
                v0 = gelu_exact(v0); v1 = gelu_exact(v1);
                v2 = gelu_exact(v2); v3 = gelu_exact(v3);
            }
            size_t o0 = (size_t)r0 * N + col;
            size_t o1 = (size_t)(r0 + 8) * N + col;
            if (OUTBF) {
                __nv_bfloat16 h0, l0, h1, l1, h2, l2, h3, l3;
                split_bf16(v0, h0, l0); split_bf16(v1, h1, l1);
                split_bf16(v2, h2, l2); split_bf16(v3, h3, l3);
                *(__nv_bfloat162*)(Ch + z * cStrideZ + o0) = __nv_bfloat162(h0, h1);
                *(__nv_bfloat162*)(Cl + z * cStrideZ + o0) = __nv_bfloat162(l0, l1);
                *(__nv_bfloat162*)(Ch + z * cStrideZ + o1) = __nv_bfloat162(h2, h3);
                *(__nv_bfloat162*)(Cl + z * cStrideZ + o1) = __nv_bfloat162(l2, l3);
            } else {
                *(float2*)(C + z * cStrideZ + o0) = make_float2(v0, v1);
                *(float2*)(C + z * cStrideZ + o1) = make_float2(v2, v3);
            }
        }
    }
}

// ---------------- fused attention ----------------
__global__ __launch_bounds__(64) void attn_kernel(
    const float* __restrict__ qb, const float* __restrict__ kb,
    const float* __restrict__ vb, const int* __restrict__ mask,
    float* __restrict__ out)
{
    const int bh = blockIdx.x;
    const int b = bh / N_HEADS;
    const int h = bh % N_HEADS;
    const int t = threadIdx.x;
    const int q = blockIdx.y * 64 + t;

    __shared__ float Ks[64 * 64];
    __shared__ float Vs[64 * 64];
    __shared__ float mb[SEQ];

#pragma unroll
    for (int j = 0; j < 4; j++) {
        int i = t + j * 64;
        mb[i] = -10000.0f * (1.0f - (float)mask[b * SEQ + i]);
    }

    const size_t qoff = ((size_t)(b * SEQ + q)) * D_MODEL + h * DH;
    float4 q4[16];
    const float4* qp = (const float4*)(qb + qoff);
#pragma unroll
    for (int i = 0; i < 16; i++) q4[i] = qp[i];

    float4 acc[16];
#pragma unroll
    for (int i = 0; i < 16; i++) acc[i] = make_float4(0.f, 0.f, 0.f, 0.f);
    float m = -1e30f, l = 0.0f;

    for (int kc = 0; kc < 4; kc++) {
        __syncthreads();
#pragma unroll
        for (int it = 0; it < 16; it++) {
            int idx = t + it * 64;
            int r = idx >> 4;
            int cc = idx & 15;
            size_t gof = ((size_t)(b * SEQ + kc * 64 + r)) * D_MODEL + h * DH + cc * 4;
            ((float4*)Ks)[idx] = *(const float4*)(kb + gof);
            ((float4*)Vs)[idx] = *(const float4*)(vb + gof);
        }
        __syncthreads();

        for (int kk = 0; kk < 64; kk++) {
            const float4* Kr = (const float4*)(Ks + kk * 64);
            float dot = 0.0f;
#pragma unroll
            for (int i = 0; i < 16; i++) {
                dot += q4[i].x * Kr[i].x + q4[i].y * Kr[i].y
                     + q4[i].z * Kr[i].z + q4[i].w * Kr[i].w;
            }
            float s  = dot * 0.125f + mb[kc * 64 + kk];
            float nm = fmaxf(m, s);
            float corr = __expf(m - nm);
            float p    = __expf(s - nm);
            l = l * corr + p;
            const float4* Vr = (const float4*)(Vs + kk * 64);
#pragma unroll
            for (int i = 0; i < 16; i++) {
                acc[i].x = fmaf(acc[i].x, corr, p * Vr[i].x);
                acc[i].y = fmaf(acc[i].y, corr, p * Vr[i].y);
                acc[i].z = fmaf(acc[i].z, corr, p * Vr[i].z);
                acc[i].w = fmaf(acc[i].w, corr, p * Vr[i].w);
            }
            m = nm;
        }
    }

    float inv = 1.0f / l;
    float4* op = (float4*)(out + qoff);
#pragma unroll
    for (int i = 0; i < 16; i++)
        op[i] = make_float4(acc[i].x * inv, acc[i].y * inv, acc[i].z * inv, acc[i].w * inv);
}

// ---------------- residual add + LayerNorm + bf16 hi/lo split ----------------
__global__ __launch_bounds__(256) void add_ln_kernel(
    float* __restrict__ x, const float* __restrict__ r,
    const float* __restrict__ g, const float* __restrict__ b,
    __nv_bfloat16* __restrict__ xh, __nv_bfloat16* __restrict__ xl)
{
    const int row = blockIdx.x;
    const int t = threadIdx.x;
    const size_t base = (size_t)row * D_MODEL;

    float v[3];
    float s = 0.f, s2 = 0.f;
#pragma unroll
    for (int j = 0; j < 3; j++) {
        int i = t + j * 256;
        float val = x[base + i] + r[base + i];
        v[j] = val;
        s += val;
        s2 += val * val;
    }
    __shared__ float sh1[256], sh2[256];
    sh1[t] = s; sh2[t] = s2;
    __syncthreads();
    for (int o = 128; o > 0; o >>= 1) {
        if (t < o) { sh1[t] += sh1[t + o]; sh2[t] += sh2[t + o]; }
        __syncthreads();
    }
    float mean = sh1[0] * (1.0f / D_MODEL);
    float var  = sh2[0] * (1.0f / D_MODEL) - mean * mean;
    float rstd = rsqrtf(var + 1e-12f);
#pragma unroll
    for (int j = 0; j < 3; j++) {
        int i = t + j * 256;
        float val = (v[j] - mean) * rstd * g[i] + b[i];
        x[base + i] = val;
        __nv_bfloat16 h, l;
        split_bf16(val, h, l);
        xh[base + i] = h;
        xl[base + i] = l;
    }
}

// ---------------- host orchestration ----------------
extern "C" void kernel_launch(void* const* d_in, const int* in_sizes, int n_in,
                              void* d_out, int out_size)
{
    (void)in_sizes; (void)n_in; (void)out_size;
    const float* in_x    = (const float*)d_in[0];
    const float* in_y    = (const float*)d_in[1];
    const int*   x_mask  = (const int*)d_in[2];
    const int*   y_mask  = (const int*)d_in[3];
    const float* ax_w = (const float*)d_in[4];
    const float* ax_b = (const float*)d_in[5];
    const float* cx_w = (const float*)d_in[6];
    const float* cx_b = (const float*)d_in[7];
    const float* fx_w1 = (const float*)d_in[8];
    const float* fx_b1 = (const float*)d_in[9];
    const float* fx_w2 = (const float*)d_in[10];
    const float* fx_b2 = (const float*)d_in[11];
    const float* ay_w = (const float*)d_in[12];
    const float* ay_b = (const float*)d_in[13];
    const float* cy_w = (const float*)d_in[14];
    const float* cy_b = (const float*)d_in[15];
    const float* fy_w1 = (const float*)d_in[16];
    const float* fy_b1 = (const float*)d_in[17];
    const float* fy_w2 = (const float*)d_in[18];
    const float* fy_b2 = (const float*)d_in[19];
    const float* lnx_g = (const float*)d_in[20];
    const float* lnx_b = (const float*)d_in[21];
    const float* lny_g = (const float*)d_in[22];
    const float* lny_b = (const float*)d_in[23];
    float* out = (float*)d_out;

    float *gx, *gy, *gqkv, *gtmp;
    __nv_bfloat16 *gxh, *gxl, *gyh, *gyl, *ghh, *ghl, *gwth, *gwtl;
    cudaGetSymbolAddress((void**)&gx,   g_x);
    cudaGetSymbolAddress((void**)&gy,   g_y);
    cudaGetSymbolAddress((void**)&gqkv, g_qkv);
    cudaGetSymbolAddress((void**)&gtmp, g_tmp);
    cudaGetSymbolAddress((void**)&gxh,  g_xh);
    cudaGetSymbolAddress((void**)&gxl,  g_xl);
    cudaGetSymbolAddress((void**)&gyh,  g_yh);
    cudaGetSymbolAddress((void**)&gyl,  g_yl);
    cudaGetSymbolAddress((void**)&ghh,  g_hh);
    cudaGetSymbolAddress((void**)&ghl,  g_hl);
    cudaGetSymbolAddress((void**)&gwth, g_wth);
    cudaGetSymbolAddress((void**)&gwtl, g_wtl);

    cudaFuncSetAttribute(mma_gemm<0,0>, cudaFuncAttributeMaxDynamicSharedMemorySize, SMEM_BYTES);
    cudaFuncSetAttribute(mma_gemm<1,1>, cudaFuncAttributeMaxDynamicSharedMemorySize, SMEM_BYTES);

    cudaMemcpyAsync(gx, in_x, MD * sizeof(float), cudaMemcpyDeviceToDevice, 0);
    cudaMemcpyAsync(gy, in_y, MD * sizeof(float), cudaMemcpyDeviceToDevice, 0);

    // weight transpose + bf16 split
    const dim3 wblk(32, 8);
    wconv_kernel<<<dim3(24, 24, 18), wblk>>>(ax_w,  gwth + OFF_AX,   gwtl + OFF_AX,   768, 768);
    wconv_kernel<<<dim3(24, 24, 18), wblk>>>(cx_w,  gwth + OFF_CX,   gwtl + OFF_CX,   768, 768);
    wconv_kernel<<<dim3(24, 24, 18), wblk>>>(ay_w,  gwth + OFF_AY,   gwtl + OFF_AY,   768, 768);
    wconv_kernel<<<dim3(24, 24, 18), wblk>>>(cy_w,  gwth + OFF_CY,   gwtl + OFF_CY,   768, 768);
    wconv_kernel<<<dim3(96, 24, 6),  wblk>>>(fx_w1, gwth + OFF_FXW1, gwtl + OFF_FXW1, 768, 3072);
    wconv_kernel<<<dim3(96, 24, 6),  wblk>>>(fy_w1, gwth + OFF_FYW1, gwtl + OFF_FYW1, 768, 3072);
    wconv_kernel<<<dim3(24, 96, 6),  wblk>>>(fx_w2, gwth + OFF_FXW2, gwtl + OFF_FXW2, 3072, 768);
    wconv_kernel<<<dim3(24, 96, 6),  wblk>>>(fy_w2, gwth + OFF_FYW2, gwtl + OFF_FYW2, 3072, 768);

    // initial activation split
    aconv_kernel<<<(int)(MD / 256), 256>>>(gx, gxh, gxl, (int)MD);
    aconv_kernel<<<(int)(MD / 256), 256>>>(gy, gyh, gyl, (int)MD);

    const dim3 gridProj(6, 16, 3);
    const dim3 gridF1(24, 16, 1);
    const dim3 gridF2(6, 16, 1);
    const dim3 gridAttn(BATCH * N_HEADS, 4, 1);

    auto attn_block = [&](float* cur, __nv_bfloat16* ch, __nv_bfloat16* cl,
                          __nv_bfloat16* kvh, __nv_bfloat16* kvl,
                          size_t woff, const float* bb, const int* mask,
                          const float* lg, const float* lb) {
        mma_gemm<0,0><<<gridProj, 256, SMEM_BYTES>>>(
            ch, cl, kvh, kvl, gwth + woff, gwtl + woff, bb,
            gqkv, nullptr, nullptr, D_MODEL, D_MODEL, (size_t)DDW, D_MODEL, MD);
        attn_kernel<<<gridAttn, 64>>>(gqkv, gqkv + MD, gqkv + 2 * MD, mask, gtmp);
        add_ln_kernel<<<MROWS, 256>>>(cur, gtmp, lg, lb, ch, cl);
    };
    auto ffn_block = [&](float* cur, __nv_bfloat16* ch, __nv_bfloat16* cl,
                         size_t w1off, const float* b1, size_t w2off, const float* b2,
                         const float* lg, const float* lb) {
        mma_gemm<1,1><<<gridF1, 256, SMEM_BYTES>>>(
            ch, cl, ch, cl, gwth + w1off, gwtl + w1off, b1,
            nullptr, ghh, ghl, DFF, D_MODEL, 0, 0, 0);
        mma_gemm<0,0><<<gridF2, 256, SMEM_BYTES>>>(
            ghh, ghl, ghh, ghl, gwth + w2off, gwtl + w2off, b2,
            gtmp, nullptr, nullptr, D_MODEL, DFF, 0, 0, 0);
        add_ln_kernel<<<MROWS, 256>>>(cur, gtmp, lg, lb, ch, cl);
    };

    for (int L = 0; L < NLAYER; L++) {
        const size_t pOff = (size_t)L * 3 * DDW;
        const size_t bOff = (size_t)L * 3 * D_MODEL;
        const size_t w1Off = (size_t)L * D_MODEL * DFF;
        const size_t w2Off = (size_t)L * DFF * D_MODEL;
        // 1) x self-attention
        attn_block(gx, gxh, gxl, gxh, gxl, OFF_AX + pOff, ax_b + bOff, x_mask,
                   lnx_g, lnx_b);
        // 2) y self-attention
        attn_block(gy, gyh, gyl, gyh, gyl, OFF_AY + pOff, ay_b + bOff, y_mask,
                   lny_g, lny_b);
        // 3) x cross-attention (q from x, kv from updated y)
        attn_block(gx, gxh, gxl, gyh, gyl, OFF_CX + pOff, cx_b + bOff, y_mask,
                   lnx_g + D_MODEL, lnx_b + D_MODEL);
        // 4) y cross-attention (q from y, kv from updated x)
        attn_block(gy, gyh, gyl, gxh, gxl, OFF_CY + pOff, cy_b + bOff, x_mask,
                   lny_g + D_MODEL, lny_b + D_MODEL);
        // 5) x FFN
        ffn_block(gx, gxh, gxl, OFF_FXW1 + w1Off, fx_b1 + (size_t)L * DFF,
                  OFF_FXW2 + w2Off, fx_b2 + (size_t)L * D_MODEL,
                  lnx_g + 2 * D_MODEL, lnx_b + 2 * D_MODEL);
        // 6) y FFN
        ffn_block(gy, gyh, gyl, OFF_FYW1 + w1Off, fy_b1 + (size_t)L * DFF,
                  OFF_FYW2 + w2Off, fy_b2 + (size_t)L * D_MODEL,
                  lny_g + 2 * D_MODEL, lny_b + 2 * D_MODEL);
    }

    cudaMemcpyAsync(out,      gx, MD * sizeof(float), cudaMemcpyDeviceToDevice, 0);
    cudaMemcpyAsync(out + MD, gy, MD * sizeof(float), cudaMemcpyDeviceToDevice, 0);
}

// round 15
// speedup vs baseline: 2.0643x; 1.2990x over previous
#include <cuda_runtime.h>
#include <cuda_bf16.h>
#include <math.h>
#include <stdint.h>

// ---------------- problem constants ----------------
#define D_MODEL 768
#define N_HEADS 12
#define DH 64
#define BATCH 8
#define SEQ 256
#define NLAYER 6
#define MROWS 2048
#define DFF 3072
#define MD ((size_t)MROWS * D_MODEL)
#define HD ((size_t)MROWS * DFF)
#define DDW (D_MODEL * D_MODEL)           // 589824

// converted-weight layout (contiguous groups; dst = gwth + mat*DDW for proj)
#define OFF_AX   0
#define OFF_CX   10616832                  // 18 * 589824
#define OFF_AY   21233664                  // 36 * DDW
#define OFF_CY   31850496                  // 54 * DDW
#define OFF_FXW1 42467328                  // 72 * DDW
#define OFF_FYW1 56623104                  // + 6*2359296
#define OFF_FXW2 70778880
#define OFF_FYW2 84934656
#define WELEMS   99090432

// ---------------- scratch (device globals; no runtime allocation) ----------------
__device__ float g_x[MROWS * D_MODEL];
__device__ float g_y[MROWS * D_MODEL];
__device__ float g_qkv[6 * MROWS * D_MODEL];     // x qkv: 0..2, y qkv: 3..5 (self-batched)
__device__ float g_tmp[2 * MROWS * D_MODEL];     // attn/ffn2 out, x then y
__device__ __nv_bfloat16 g_xh[MROWS * D_MODEL];
__device__ __nv_bfloat16 g_xl[MROWS * D_MODEL];
__device__ __nv_bfloat16 g_yh[MROWS * D_MODEL];
__device__ __nv_bfloat16 g_yl[MROWS * D_MODEL];
__device__ __nv_bfloat16 g_hh[2 * MROWS * DFF];  // ffn hidden, x then y
__device__ __nv_bfloat16 g_hl[2 * MROWS * DFF];
__device__ __nv_bfloat16 g_wth[WELEMS];
__device__ __nv_bfloat16 g_wtl[WELEMS];

// ---------------- helpers ----------------
__device__ __forceinline__ void cp_async16(void* smemp, const void* gmem) {
    unsigned saddr = (unsigned)__cvta_generic_to_shared(smemp);
    asm volatile("cp.async.cg.shared.global [%0], [%1], 16;\n" :: "r"(saddr), "l"(gmem));
}
__device__ __forceinline__ void cp_commit() {
    asm volatile("cp.async.commit_group;\n" ::: "memory");
}
__device__ __forceinline__ void cp_wait1() {
    asm volatile("cp.async.wait_group 1;\n" ::: "memory");
}
__device__ __forceinline__ void cp_wait0() {
    asm volatile("cp.async.wait_group 0;\n" ::: "memory");
}
__device__ __forceinline__ uint32_t ld32(const void* p) {
    return *(const uint32_t*)p;
}
__device__ __forceinline__ void mma_bf16(float* c, const uint32_t* a, uint32_t b0, uint32_t b1) {
    asm volatile(
        "mma.sync.aligned.m16n8k16.row.col.f32.bf16.bf16.f32 "
        "{%0,%1,%2,%3}, {%4,%5,%6,%7}, {%8,%9}, {%0,%1,%2,%3};"
        : "+f"(c[0]), "+f"(c[1]), "+f"(c[2]), "+f"(c[3])
        : "r"(a[0]), "r"(a[1]), "r"(a[2]), "r"(a[3]), "r"(b0), "r"(b1));
}
__device__ __forceinline__ float gelu_exact(float x) {
    return 0.5f * x * (1.0f + erff(x * 0.70710678118654752f));
}
__device__ __forceinline__ void split_bf16(float v, __nv_bfloat16& h, __nv_bfloat16& l) {
    h = __float2bfloat16(v);
    l = __float2bfloat16(v - __bfloat162float(h));
}

// ---------------- weight transpose + bf16 hi/lo split (4-source batched) ----------------
// in: up to 4 weight groups, each matsPer matrices of [K][N] fp32
// out: dh/dl + mat*K*N, transposed to [N][K] bf16
__global__ __launch_bounds__(256) void wconv4_kernel(
    const float* __restrict__ s0, const float* __restrict__ s1,
    const float* __restrict__ s2, const float* __restrict__ s3,
    __nv_bfloat16* __restrict__ dh, __nv_bfloat16* __restrict__ dl,
    int K, int N, int matsPer)
{
    __shared__ float tile[32][33];
    const int mat = blockIdx.z;
    const int grp = mat / matsPer;
    const int loc = mat - grp * matsPer;
    const float* sb = (grp == 0) ? s0 : (grp == 1) ? s1 : (grp == 2) ? s2 : s3;
    const float* s = sb + (size_t)loc * K * N;
    const size_t dbase = (size_t)mat * K * N;
    const int n0 = blockIdx.x * 32, k0 = blockIdx.y * 32;
    const int tx = threadIdx.x, ty = threadIdx.y;   // (32, 8)
#pragma unroll
    for (int j = 0; j < 4; j++)
        tile[ty + j * 8][tx] = s[(size_t)(k0 + ty + j * 8) * N + n0 + tx];
    __syncthreads();
#pragma unroll
    for (int j = 0; j < 4; j++) {
        int nl = ty + j * 8;
        float v = tile[tx][nl];
        __nv_bfloat16 h, l;
        split_bf16(v, h, l);
        size_t o = dbase + (size_t)(n0 + nl) * K + k0 + tx;
        dh[o] = h; dl[o] = l;
    }
}

// fp32 -> bf16 hi/lo for both x and y in one launch
__global__ __launch_bounds__(256) void aconv2_kernel(
    const float* __restrict__ sx, const float* __restrict__ sy,
    __nv_bfloat16* __restrict__ xh, __nv_bfloat16* __restrict__ xl,
    __nv_bfloat16* __restrict__ yh, __nv_bfloat16* __restrict__ yl)
{
    size_t i = (size_t)blockIdx.x * 256 + threadIdx.x;
    __nv_bfloat16 h, l;
    if (i < MD) {
        split_bf16(sx[i], h, l);
        xh[i] = h; xl[i] = l;
    } else {
        size_t j = i - MD;
        split_bf16(sy[j], h, l);
        yh[j] = h; yl[j] = l;
    }
}

// ---------------- bf16 split GEMM via mma.sync (HMMA) ----------------
// C[z] = act(A(z) @ W(z)^T-stored + bias(z)); A=Ah+Al, W=Wh+Wl; 3 of 4 terms.
// Tiles 128x128x32, 8 warps, warp tile 32x64. smem row stride 40 bf16.
// z selects A (z<zA: A0 else A1) and W/bias (z<zW: B0[z] else B1[z-zW]).
#define TILE_B   10240                      // 128 * 40 * 2 bytes
#define BUF_B    (4 * TILE_B)               // Ah, Al, Bh, Bl
#define SMEM_BYTES (2 * BUF_B)              // 81920

template<int ACT, int OUTBF>
__global__ __launch_bounds__(256) void mma_gemm(
    const __nv_bfloat16* __restrict__ A0h, const __nv_bfloat16* __restrict__ A0l,
    const __nv_bfloat16* __restrict__ A1h, const __nv_bfloat16* __restrict__ A1l, int zA,
    const __nv_bfloat16* __restrict__ B0h, const __nv_bfloat16* __restrict__ B0l,
    const __nv_bfloat16* __restrict__ B1h, const __nv_bfloat16* __restrict__ B1l, int zW,
    const float* __restrict__ bias0, const float* __restrict__ bias1,
    float* __restrict__ C, __nv_bfloat16* __restrict__ Ch, __nv_bfloat16* __restrict__ Cl,
    int N, int K, size_t wStrideZ, int biasStrideZ, size_t cStrideZ)
{
    extern __shared__ char smem[];
    const int z = blockIdx.z;
    const __nv_bfloat16* __restrict__ Ah = (z < zA) ? A0h : A1h;
    const __nv_bfloat16* __restrict__ Al = (z < zA) ? A0l : A1l;
    const int zr = (z < zW) ? z : z - zW;
    const __nv_bfloat16* __restrict__ Bh = ((z < zW) ? B0h : B1h) + (size_t)zr * wStrideZ;
    const __nv_bfloat16* __restrict__ Bl = ((z < zW) ? B0l : B1l) + (size_t)zr * wStrideZ;
    const float* __restrict__ bias = ((z < zW) ? bias0 : bias1) + (size_t)zr * biasStrideZ;

    const int t = threadIdx.x;
    const int warp = t >> 5;
    const int lid  = t & 31;
    const int g  = lid >> 2;        // 0..7
    const int tg = lid & 3;         // 0..3
    const int warp_m = warp >> 1;   // 0..3  -> 32-row strip
    const int warp_n = warp & 1;    // 0..1  -> 64-col strip
    const int rowBase = blockIdx.y * 128;
    const int colBase = blockIdx.x * 128;

    const __nv_bfloat16* Agh = Ah + (size_t)rowBase * K;
    const __nv_bfloat16* Agl = Al + (size_t)rowBase * K;
    const __nv_bfloat16* Bgh = Bh + (size_t)colBase * K;
    const __nv_bfloat16* Bgl = Bl + (size_t)colBase * K;

    float c[2][8][4];
#pragma unroll
    for (int m = 0; m < 2; m++)
#pragma unroll
        for (int n = 0; n < 8; n++)
#pragma unroll
            for (int i = 0; i < 4; i++) c[m][n][i] = 0.0f;

    auto load_chunk = [&](int buf, int kt) {
        char* base = smem + buf * BUF_B;
#pragma unroll
        for (int half = 0; half < 2; half++) {
            int idx = t + half * 256;       // 0..511
            int row = idx >> 2;
            int q   = idx & 3;
            size_t go = (size_t)row * K + kt + q * 8;
            uint32_t so = row * 80 + q * 16;
            cp_async16(base + so,                Agh + go);
            cp_async16(base + TILE_B + so,       Agl + go);
            cp_async16(base + 2 * TILE_B + so,   Bgh + go);
            cp_async16(base + 3 * TILE_B + so,   Bgl + go);
        }
        cp_commit();
    };

    auto compute_chunk = [&](int buf) {
        const char* base = smem + buf * BUF_B;
        const __nv_bfloat16* AsH = (const __nv_bfloat16*)(base);
        const __nv_bfloat16* AsL = (const __nv_bfloat16*)(base + TILE_B);
        const __nv_bfloat16* BsH = (const __nv_bfloat16*)(base + 2 * TILE_B);
        const __nv_bfloat16* BsL = (const __nv_bfloat16*)(base + 3 * TILE_B);
#pragma unroll
        for (int ks = 0; ks < 2; ks++) {
            const int k0 = ks * 16 + tg * 2;
            uint32_t ah[2][4], al[2][4];
#pragma unroll
            for (int m = 0; m < 2; m++) {
                int r0 = warp_m * 32 + m * 16 + g;
                ah[m][0] = ld32(AsH + r0 * 40 + k0);
                ah[m][1] = ld32(AsH + (r0 + 8) * 40 + k0);
                ah[m][2] = ld32(AsH + r0 * 40 + k0 + 8);
                ah[m][3] = ld32(AsH + (r0 + 8) * 40 + k0 + 8);
                al[m][0] = ld32(AsL + r0 * 40 + k0);
                al[m][1] = ld32(AsL + (r0 + 8) * 40 + k0);
                al[m][2] = ld32(AsL + r0 * 40 + k0 + 8);
                al[m][3] = ld32(AsL + (r0 + 8) * 40 + k0 + 8);
            }
#pragma unroll
            for (int n = 0; n < 8; n++) {
                int br = warp_n * 64 + n * 8 + g;
                uint32_t bh0 = ld32(BsH + br * 40 + k0);
                uint32_t bh1 = ld32(BsH + br * 40 + k0 + 8);
                uint32_t bl0 = ld32(BsL + br * 40 + k0);
                uint32_t bl1 = ld32(BsL + br * 40 + k0 + 8);
#pragma unroll
                for (int m = 0; m < 2; m++) {
                    mma_bf16(c[m][n], ah[m], bh0, bh1);   // Ah*Bh
                    mma_bf16(c[m][n], ah[m], bl0, bl1);   // Ah*Bl
                    mma_bf16(c[m][n], al[m], bh0, bh1);   // Al*Bh
                }
            }
        }
    };

    const int nc = K / 32;
    load_chunk(0, 0);
    for (int ck = 0; ck < nc; ck++) {
        if (ck + 1 < nc) {
            load_chunk((ck + 1) & 1, (ck + 1) * 32);
            cp_wait1();
        } else {
            cp_wait0();
        }
        __syncthreads();
        compute_chunk(ck & 1);
        __syncthreads();
    }

    // epilogue: bias (+GELU), store fp32 or bf16 hi/lo split
#pragma unroll
    for (int m = 0; m < 2; m++) {
        int r0 = rowBase + warp_m * 32 + m * 16 + g;
#pragma unroll
        for (int n = 0; n < 8; n++) {
            int col = colBase + warp_n * 64 + n * 8 + tg * 2;
            float2 bv = *(const float2*)(bias + col);
            float v0 = c[m][n][0] + bv.x;
            float v1 = c[m][n][1] + bv.y;
            float v2 = c[m][n][2] + bv.x;
            float v3 = c[m][n][3] + bv.y;
            if (ACT == 1) {
                v0 = gelu_exact(v0); v1 = gelu_exact(v1);
                v2 = gelu_exact(v2); v3 = gelu_exact(v3);
            }
            size_t o0 = (size_t)r0 * N + col;
            size_t o1 = (size_t)(r0 + 8) * N + col;
            if (OUTBF) {
                __nv_bfloat16 h0, l0, h1, l1, h2, l2, h3, l3;
                split_bf16(v0, h0, l0); split_bf16(v1, h1, l1);
                split_bf16(v2, h2, l2); split_bf16(v3, h3, l3);
                *(__nv_bfloat162*)(Ch + z * cStrideZ + o0) = __nv_bfloat162(h0, h1);
                *(__nv_bfloat162*)(Cl + z * cStrideZ + o0) = __nv_bfloat162(l0, l1);
                *(__nv_bfloat162*)(Ch + z * cStrideZ + o1) = __nv_bfloat162(h2, h3);
                *(__nv_bfloat162*)(Cl + z * cStrideZ + o1) = __nv_bfloat162(l2, l3);
            } else {
                *(float2*)(C + z * cStrideZ + o0) = make_float2(v0, v1);
                *(float2*)(C + z * cStrideZ + o1) = make_float2(v2, v3);
            }
        }
    }
}

// ---------------- fused attention (z-batched over streams) ----------------
// grid (B*H, 4, nz). qkv layout: stream z occupies qkv + z*3*MD (q, k, v).
__global__ __launch_bounds__(64) void attn_kernel(
    const float* __restrict__ qkv, const int* __restrict__ mask0,
    const int* __restrict__ mask1, float* __restrict__ outb)
{
    const int z = blockIdx.z;
    const float* __restrict__ qb = qkv + (size_t)z * 3 * MD;
    const float* __restrict__ kb = qb + MD;
    const float* __restrict__ vb = qb + 2 * MD;
    const int* __restrict__ mask = (z == 0) ? mask0 : mask1;
    float* __restrict__ out = outb + (size_t)z * MD;

    const int bh = blockIdx.x;
    const int b = bh / N_HEADS;
    const int h = bh % N_HEADS;
    const int t = threadIdx.x;
    const int q = blockIdx.y * 64 + t;

    __shared__ float Ks[64 * 64];
    __shared__ float Vs[64 * 64];
    __shared__ float mb[SEQ];

#pragma unroll
    for (int j = 0; j < 4; j++) {
        int i = t + j * 64;
        mb[i] = -10000.0f * (1.0f - (float)mask[b * SEQ + i]);
    }

    const size_t qoff = ((size_t)(b * SEQ + q)) * D_MODEL + h * DH;
    float4 q4[16];
    const float4* qp = (const float4*)(qb + qoff);
#pragma unroll
    for (int i = 0; i < 16; i++) q4[i] = qp[i];

    float4 acc[16];
#pragma unroll
    for (int i = 0; i < 16; i++) acc[i] = make_float4(0.f, 0.f, 0.f, 0.f);
    float m = -1e30f, l = 0.0f;

    for (int kc = 0; kc < 4; kc++) {
        __syncthreads();
#pragma unroll
        for (int it = 0; it < 16; it++) {
            int idx = t + it * 64;
            int r = idx >> 4;
            int cc = idx & 15;
            size_t gof = ((size_t)(b * SEQ + kc * 64 + r)) * D_MODEL + h * DH + cc * 4;
            ((float4*)Ks)[idx] = *(const float4*)(kb + gof);
            ((float4*)Vs)[idx] = *(const float4*)(vb + gof);
        }
        __syncthreads();

        for (int kk = 0; kk < 64; kk++) {
            const float4* Kr = (const float4*)(Ks + kk * 64);
            float dot = 0.0f;
#pragma unroll
            for (int i = 0; i < 16; i++) {
                dot += q4[i].x * Kr[i].x + q4[i].y * Kr[i].y
                     + q4[i].z * Kr[i].z + q4[i].w * Kr[i].w;
            }
            float s  = dot * 0.125f + mb[kc * 64 + kk];
            float nm = fmaxf(m, s);
            float corr = __expf(m - nm);
            float p    = __expf(s - nm);
            l = l * corr + p;
            const float4* Vr = (const float4*)(Vs + kk * 64);
#pragma unroll
            for (int i = 0; i < 16; i++) {
                acc[i].x = fmaf(acc[i].x, corr, p * Vr[i].x);
                acc[i].y = fmaf(acc[i].y, corr, p * Vr[i].y);
                acc[i].z = fmaf(acc[i].z, corr, p * Vr[i].z);
                acc[i].w = fmaf(acc[i].w, corr, p * Vr[i].w);
            }
            m = nm;
        }
    }

    float inv = 1.0f / l;
    float4* op = (float4*)(out + qoff);
#pragma unroll
    for (int i = 0; i < 16; i++)
        op[i] = make_float4(acc[i].x * inv, acc[i].y * inv, acc[i].z * inv, acc[i].w * inv);
}

// ---------------- residual add + LayerNorm + bf16 split (2-stream batched) ----------------
// rows [0, halfRows) -> stream 0, rows [halfRows, grid) -> stream 1.
// residual r is contiguous over all rows.
__global__ __launch_bounds__(256) void add_ln_kernel(
    float* __restrict__ x0, float* __restrict__ x1, const float* __restrict__ r,
    const float* __restrict__ g0, const float* __restrict__ b0,
    const float* __restrict__ g1, const float* __restrict__ b1,
    __nv_bfloat16* __restrict__ xh0, __nv_bfloat16* __restrict__ xl0,
    __nv_bfloat16* __restrict__ xh1, __nv_bfloat16* __restrict__ xl1,
    int halfRows)
{
    const int row = blockIdx.x;
    const int t = threadIdx.x;
    float* x; const float* g; const float* b;
    __nv_bfloat16 *xh, *xl;
    int lrow;
    if (row < halfRows) { x = x0; g = g0; b = b0; xh = xh0; xl = xl0; lrow = row; }
    else                { x = x1; g = g1; b = b1; xh = xh1; xl = xl1; lrow = row - halfRows; }
    const size_t base  = (size_t)lrow * D_MODEL;
    const size_t rbase = (size_t)row * D_MODEL;

    float v[3];
    float s = 0.f, s2 = 0.f;
#pragma unroll
    for (int j = 0; j < 3; j++) {
        int i = t + j * 256;
        float val = x[base + i] + r[rbase + i];
        v[j] = val;
        s += val;
        s2 += val * val;
    }
    __shared__ float sh1[256], sh2[256];
    sh1[t] = s; sh2[t] = s2;
    __syncthreads();
    for (int o = 128; o > 0; o >>= 1) {
        if (t < o) { sh1[t] += sh1[t + o]; sh2[t] += sh2[t + o]; }
        __syncthreads();
    }
    float mean = sh1[0] * (1.0f / D_MODEL);
    float var  = sh2[0] * (1.0f / D_MODEL) - mean * mean;
    float rstd = rsqrtf(var + 1e-12f);
#pragma unroll
    for (int j = 0; j < 3; j++) {
        int i = t + j * 256;
        float val = (v[j] - mean) * rstd * g[i] + b[i];
        x[base + i] = val;
        __nv_bfloat16 h, l;
        split_bf16(val, h, l);
        xh[base + i] = h;
        xl[base + i] = l;
    }
}

// ---------------- host orchestration ----------------
extern "C" void kernel_launch(void* const* d_in, const int* in_sizes, int n_in,
                              void* d_out, int out_size)
{
    (void)in_sizes; (void)n_in; (void)out_size;
    const float* in_x    = (const float*)d_in[0];
    const float* in_y    = (const float*)d_in[1];
    const int*   x_mask  = (const int*)d_in[2];
    const int*   y_mask  = (const int*)d_in[3];
    const float* ax_w = (const float*)d_in[4];
    const float* ax_b = (const float*)d_in[5];
    const float* cx_w = (const float*)d_in[6];
    const float* cx_b = (const float*)d_in[7];
    const float* fx_w1 = (const float*)d_in[8];
    const float* fx_b1 = (const float*)d_in[9];
    const float* fx_w2 = (const float*)d_in[10];
    const float* fx_b2 = (const float*)d_in[11];
    const float* ay_w = (const float*)d_in[12];
    const float* ay_b = (const float*)d_in[13];
    const float* cy_w = (const float*)d_in[14];
    const float* cy_b = (const float*)d_in[15];
    const float* fy_w1 = (const float*)d_in[16];
    const float* fy_b1 = (const float*)d_in[17];
    const float* fy_w2 = (const float*)d_in[18];
    const float* fy_b2 = (const float*)d_in[19];
    const float* lnx_g = (const float*)d_in[20];
    const float* lnx_b = (const float*)d_in[21];
    const float* lny_g = (const float*)d_in[22];
    const float* lny_b = (const float*)d_in[23];
    float* out = (float*)d_out;

    float *gx, *gy, *gqkv, *gtmp;
    __nv_bfloat16 *gxh, *gxl, *gyh, *gyl, *ghh, *ghl, *gwth, *gwtl;
    cudaGetSymbolAddress((void**)&gx,   g_x);
    cudaGetSymbolAddress((void**)&gy,   g_y);
    cudaGetSymbolAddress((void**)&gqkv, g_qkv);
    cudaGetSymbolAddress((void**)&gtmp, g_tmp);
    cudaGetSymbolAddress((void**)&gxh,  g_xh);
    cudaGetSymbolAddress((void**)&gxl,  g_xl);
    cudaGetSymbolAddress((void**)&gyh,  g_yh);
    cudaGetSymbolAddress((void**)&gyl,  g_yl);
    cudaGetSymbolAddress((void**)&ghh,  g_hh);
    cudaGetSymbolAddress((void**)&ghl,  g_hl);
    cudaGetSymbolAddress((void**)&gwth, g_wth);
    cudaGetSymbolAddress((void**)&gwtl, g_wtl);

    cudaFuncSetAttribute(mma_gemm<0,0>, cudaFuncAttributeMaxDynamicSharedMemorySize, SMEM_BYTES);
    cudaFuncSetAttribute(mma_gemm<1,1>, cudaFuncAttributeMaxDynamicSharedMemorySize, SMEM_BYTES);

    cudaMemcpyAsync(gx, in_x, MD * sizeof(float), cudaMemcpyDeviceToDevice, 0);
    cudaMemcpyAsync(gy, in_y, MD * sizeof(float), cudaMemcpyDeviceToDevice, 0);

    // weight transpose + bf16 split (3 batched launches)
    const dim3 wblk(32, 8);
    // 72 projection matrices: ax(18), cx(18), ay(18), cy(18) -> contiguous dst
    wconv4_kernel<<<dim3(24, 24, 72), wblk>>>(ax_w, cx_w, ay_w, cy_w,
                                              gwth + OFF_AX, gwtl + OFF_AX, 768, 768, 18);
    // 12 FFN1 matrices: fx_w1(6), fy_w1(6)
    wconv4_kernel<<<dim3(96, 24, 12), wblk>>>(fx_w1, fy_w1, fx_w1, fy_w1,
                                              gwth + OFF_FXW1, gwtl + OFF_FXW1, 768, 3072, 6);
    // 12 FFN2 matrices: fx_w2(6), fy_w2(6)
    wconv4_kernel<<<dim3(24, 96, 12), wblk>>>(fx_w2, fy_w2, fx_w2, fy_w2,
                                              gwth + OFF_FXW2, gwtl + OFF_FXW2, 3072, 768, 6);

    // initial activation split (both streams)
    aconv2_kernel<<<(int)(2 * MD / 256), 256>>>(gx, gy, gxh, gxl, gyh, gyl);

    const dim3 gridSelf(6, 16, 6);
    const dim3 gridCross(6, 16, 3);
    const dim3 gridF1(24, 16, 2);
    const dim3 gridF2(6, 16, 2);

    for (int L = 0; L < NLAYER; L++) {
        const size_t pOff  = (size_t)L * 3 * DDW;
        const size_t bOff  = (size_t)L * 3 * D_MODEL;
        const size_t w1Off = (size_t)L * D_MODEL * DFF;
        const size_t w2Off = (size_t)L * DFF * D_MODEL;

        // ---- 1+2) batched self-attention (x and y) ----
        mma_gemm<0,0><<<gridSelf, 256, SMEM_BYTES>>>(
            gxh, gxl, gyh, gyl, 3,
            gwth + OFF_AX + pOff, gwtl + OFF_AX + pOff,
            gwth + OFF_AY + pOff, gwtl + OFF_AY + pOff, 3,
            ax_b + bOff, ay_b + bOff,
            gqkv, nullptr, nullptr, D_MODEL, D_MODEL, (size_t)DDW, D_MODEL, MD);
        attn_kernel<<<dim3(BATCH * N_HEADS, 4, 2), 64>>>(gqkv, x_mask, y_mask, gtmp);
        add_ln_kernel<<<2 * MROWS, 256>>>(gx, gy, gtmp,
            lnx_g, lnx_b, lny_g, lny_b, gxh, gxl, gyh, gyl, MROWS);

        // ---- 3) x cross-attention (q from x, kv from updated y) ----
        mma_gemm<0,0><<<gridCross, 256, SMEM_BYTES>>>(
            gxh, gxl, gyh, gyl, 1,
            gwth + OFF_CX + pOff, gwtl + OFF_CX + pOff,
            gwth + OFF_CX + pOff, gwtl + OFF_CX + pOff, 8,
            cx_b + bOff, cx_b + bOff,
            gqkv, nullptr, nullptr, D_MODEL, D_MODEL, (size_t)DDW, D_MODEL, MD);
        attn_kernel<<<dim3(BATCH * N_HEADS, 4, 1), 64>>>(gqkv, y_mask, y_mask, gtmp);
        add_ln_kernel<<<MROWS, 256>>>(gx, gx, gtmp,
            lnx_g + D_MODEL, lnx_b + D_MODEL, lnx_g + D_MODEL, lnx_b + D_MODEL,
            gxh, gxl, gxh, gxl, MROWS);

        // ---- 4) y cross-attention (q from y, kv from updated x) ----
        mma_gemm<0,0><<<gridCross, 256, SMEM_BYTES>>>(
            gyh, gyl, gxh, gxl, 1,
            gwth + OFF_CY + pOff, gwtl + OFF_CY + pOff,
            gwth + OFF_CY + pOff, gwtl + OFF_CY + pOff, 8,
            cy_b + bOff, cy_b + bOff,
            gqkv, nullptr, nullptr, D_MODEL, D_MODEL, (size_t)DDW, D_MODEL, MD);
        attn_kernel<<<dim3(BATCH * N_HEADS, 4, 1), 64>>>(gqkv, x_mask, x_mask, gtmp);
        add_ln_kernel<<<MROWS, 256>>>(gy, gy, gtmp,
            lny_g + D_MODEL, lny_b + D_MODEL, lny_g + D_MODEL, lny_b + D_MODEL,
            gyh, gyl, gyh, gyl, MROWS);

        // ---- 5+6) batched FFN (x and y) ----
        mma_gemm<1,1><<<gridF1, 256, SMEM_BYTES>>>(
            gxh, gxl, gyh, gyl, 1,
            gwth + OFF_FXW1 + w1Off, gwtl + OFF_FXW1 + w1Off,
            gwth + OFF_FYW1 + w1Off, gwtl + OFF_FYW1 + w1Off, 1,
            fx_b1 + (size_t)L * DFF, fy_b1 + (size_t)L * DFF,
            nullptr, ghh, ghl, DFF, D_MODEL, 0, 0, HD);
        mma_gemm<0,0><<<gridF2, 256, SMEM_BYTES>>>(
            ghh, ghl, ghh + HD, ghl + HD, 1,
            gwth + OFF_FXW2 + w2Off, gwtl + OFF_FXW2 + w2Off,
            gwth + OFF_FYW2 + w2Off, gwtl + OFF_FYW2 + w2Off, 1,
            fx_b2 + (size_t)L * D_MODEL, fy_b2 + (size_t)L * D_MODEL,
            gtmp, nullptr, nullptr, D_MODEL, DFF, 0, 0, MD);
        add_ln_kernel<<<2 * MROWS, 256>>>(gx, gy, gtmp,
            lnx_g + 2 * D_MODEL, lnx_b + 2 * D_MODEL,
            lny_g + 2 * D_MODEL, lny_b + 2 * D_MODEL,
            gxh, gxl, gyh, gyl, MROWS);
    }

    cudaMemcpyAsync(out,      gx, MD * sizeof(float), cudaMemcpyDeviceToDevice, 0);
    cudaMemcpyAsync(out + MD, gy, MD * sizeof(float), cudaMemcpyDeviceToDevice, 0);
}

// round 16
// speedup vs baseline: 2.1059x; 1.0201x over previous
#include <cuda_runtime.h>
#include <cuda_bf16.h>
#include <math.h>
#include <stdint.h>

// ---------------- problem constants ----------------
#define D_MODEL 768
#define N_HEADS 12
#define DH 64
#define BATCH 8
#define SEQ 256
#define NLAYER 6
#define MROWS 2048
#define DFF 3072
#define MD ((size_t)MROWS * D_MODEL)
#define HD ((size_t)MROWS * DFF)
#define DDW (D_MODEL * D_MODEL)           // 589824

// converted-weight layout (contiguous groups)
#define OFF_AX   0
#define OFF_CX   10616832                  // 18 * 589824
#define OFF_AY   21233664
#define OFF_CY   31850496
#define OFF_FXW1 42467328
#define OFF_FYW1 56623104
#define OFF_FXW2 70778880
#define OFF_FYW2 84934656
#define WELEMS   99090432

// ---------------- scratch (device globals; no runtime allocation) ----------------
__device__ float g_x[MROWS * D_MODEL];
__device__ float g_y[MROWS * D_MODEL];
__device__ float g_qkv[6 * MROWS * D_MODEL];     // x qkv: 0..2, y qkv: 3..5
__device__ float g_tmp[2 * MROWS * D_MODEL];
__device__ __nv_bfloat16 g_xh[MROWS * D_MODEL];
__device__ __nv_bfloat16 g_xl[MROWS * D_MODEL];
__device__ __nv_bfloat16 g_yh[MROWS * D_MODEL];
__device__ __nv_bfloat16 g_yl[MROWS * D_MODEL];
__device__ __nv_bfloat16 g_hh[2 * MROWS * DFF];
__device__ __nv_bfloat16 g_hl[2 * MROWS * DFF];
__device__ __nv_bfloat16 g_wth[WELEMS];
__device__ __nv_bfloat16 g_wtl[WELEMS];

// ---------------- helpers ----------------
__device__ __forceinline__ void cp_async16(void* smemp, const void* gmem) {
    unsigned saddr = (unsigned)__cvta_generic_to_shared(smemp);
    asm volatile("cp.async.cg.shared.global [%0], [%1], 16;\n" :: "r"(saddr), "l"(gmem));
}
__device__ __forceinline__ void cp_commit() {
    asm volatile("cp.async.commit_group;\n" ::: "memory");
}
__device__ __forceinline__ void cp_wait1() {
    asm volatile("cp.async.wait_group 1;\n" ::: "memory");
}
__device__ __forceinline__ void cp_wait0() {
    asm volatile("cp.async.wait_group 0;\n" ::: "memory");
}
__device__ __forceinline__ void ldsm4(uint32_t& r0, uint32_t& r1, uint32_t& r2, uint32_t& r3,
                                      uint32_t saddr) {
    asm volatile("ldmatrix.sync.aligned.m8n8.x4.shared.b16 {%0,%1,%2,%3}, [%4];"
                 : "=r"(r0), "=r"(r1), "=r"(r2), "=r"(r3) : "r"(saddr));
}
__device__ __forceinline__ void mma_bf16(float* c, const uint32_t* a, uint32_t b0, uint32_t b1) {
    asm volatile(
        "mma.sync.aligned.m16n8k16.row.col.f32.bf16.bf16.f32 "
        "{%0,%1,%2,%3}, {%4,%5,%6,%7}, {%8,%9}, {%0,%1,%2,%3};"
        : "+f"(c[0]), "+f"(c[1]), "+f"(c[2]), "+f"(c[3])
        : "r"(a[0]), "r"(a[1]), "r"(a[2]), "r"(a[3]), "r"(b0), "r"(b1));
}
__device__ __forceinline__ float gelu_exact(float x) {
    return 0.5f * x * (1.0f + erff(x * 0.70710678118654752f));
}
__device__ __forceinline__ void split_bf16(float v, __nv_bfloat16& h, __nv_bfloat16& l) {
    h = __float2bfloat16(v);
    l = __float2bfloat16(v - __bfloat162float(h));
}

// ---------------- weight transpose + bf16 hi/lo split (4-source batched) ----------------
__global__ __launch_bounds__(256) void wconv4_kernel(
    const float* __restrict__ s0, const float* __restrict__ s1,
    const float* __restrict__ s2, const float* __restrict__ s3,
    __nv_bfloat16* __restrict__ dh, __nv_bfloat16* __restrict__ dl,
    int K, int N, int matsPer)
{
    __shared__ float tile[32][33];
    const int mat = blockIdx.z;
    const int grp = mat / matsPer;
    const int loc = mat - grp * matsPer;
    const float* sb = (grp == 0) ? s0 : (grp == 1) ? s1 : (grp == 2) ? s2 : s3;
    const float* s = sb + (size_t)loc * K * N;
    const size_t dbase = (size_t)mat * K * N;
    const int n0 = blockIdx.x * 32, k0 = blockIdx.y * 32;
    const int tx = threadIdx.x, ty = threadIdx.y;   // (32, 8)
#pragma unroll
    for (int j = 0; j < 4; j++)
        tile[ty + j * 8][tx] = s[(size_t)(k0 + ty + j * 8) * N + n0 + tx];
    __syncthreads();
#pragma unroll
    for (int j = 0; j < 4; j++) {
        int nl = ty + j * 8;
        float v = tile[tx][nl];
        __nv_bfloat16 h, l;
        split_bf16(v, h, l);
        size_t o = dbase + (size_t)(n0 + nl) * K + k0 + tx;
        dh[o] = h; dl[o] = l;
    }
}

// fp32 -> bf16 hi/lo for both x and y in one launch
__global__ __launch_bounds__(256) void aconv2_kernel(
    const float* __restrict__ sx, const float* __restrict__ sy,
    __nv_bfloat16* __restrict__ xh, __nv_bfloat16* __restrict__ xl,
    __nv_bfloat16* __restrict__ yh, __nv_bfloat16* __restrict__ yl)
{
    size_t i = (size_t)blockIdx.x * 256 + threadIdx.x;
    __nv_bfloat16 h, l;
    if (i < MD) {
        split_bf16(sx[i], h, l);
        xh[i] = h; xl[i] = l;
    } else {
        size_t j = i - MD;
        split_bf16(sy[j], h, l);
        yh[j] = h; yl[j] = l;
    }
}

// ---------------- bf16 split GEMM via mma.sync + ldmatrix ----------------
// C[z] = act(A(z) @ W(z)^T-stored + bias(z)); A=Ah+Al, W=Wh+Wl; 3 of 4 terms.
// 128x128x32 tiles, 8 warps (warp 32x64). smem row stride 40 bf16 (80B):
// conflict-free for both cp.async rows and ldmatrix 8-row phases.
#define TILE_B   10240                      // 128 * 40 * 2 bytes
#define BUF_B    (4 * TILE_B)               // Ah, Al, Bh, Bl
#define SMEM_BYTES (2 * BUF_B)              // 81920

template<int ACT, int OUTBF>
__global__ __launch_bounds__(256) void mma_gemm(
    const __nv_bfloat16* __restrict__ A0h, const __nv_bfloat16* __restrict__ A0l,
    const __nv_bfloat16* __restrict__ A1h, const __nv_bfloat16* __restrict__ A1l, int zA,
    const __nv_bfloat16* __restrict__ B0h, const __nv_bfloat16* __restrict__ B0l,
    const __nv_bfloat16* __restrict__ B1h, const __nv_bfloat16* __restrict__ B1l, int zW,
    const float* __restrict__ bias0, const float* __restrict__ bias1,
    float* __restrict__ C, __nv_bfloat16* __restrict__ Ch, __nv_bfloat16* __restrict__ Cl,
    int N, int K, size_t wStrideZ, int biasStrideZ, size_t cStrideZ)
{
    extern __shared__ char smem[];
    const int z = blockIdx.z;
    const __nv_bfloat16* __restrict__ Ah = (z < zA) ? A0h : A1h;
    const __nv_bfloat16* __restrict__ Al = (z < zA) ? A0l : A1l;
    const int zr = (z < zW) ? z : z - zW;
    const __nv_bfloat16* __restrict__ Bh = ((z < zW) ? B0h : B1h) + (size_t)zr * wStrideZ;
    const __nv_bfloat16* __restrict__ Bl = ((z < zW) ? B0l : B1l) + (size_t)zr * wStrideZ;
    const float* __restrict__ bias = ((z < zW) ? bias0 : bias1) + (size_t)zr * biasStrideZ;

    const int t = threadIdx.x;
    const int warp = t >> 5;
    const int lid  = t & 31;
    const int g  = lid >> 2;        // 0..7
    const int tg = lid & 3;         // 0..3
    const int warp_m = warp >> 1;   // 0..3  -> 32-row strip
    const int warp_n = warp & 1;    // 0..1  -> 64-col strip
    const int rowBase = blockIdx.y * 128;
    const int colBase = blockIdx.x * 128;

    const uint32_t smem_b = (uint32_t)__cvta_generic_to_shared(smem);

    // ldmatrix lane geometry
    const int sub = lid >> 3;       // 0..3 (8x8 matrix index within x4)
    const int rin = lid & 7;        // row within matrix

    const __nv_bfloat16* Agh = Ah + (size_t)rowBase * K;
    const __nv_bfloat16* Agl = Al + (size_t)rowBase * K;
    const __nv_bfloat16* Bgh = Bh + (size_t)colBase * K;
    const __nv_bfloat16* Bgl = Bl + (size_t)colBase * K;

    float c[2][8][4];
#pragma unroll
    for (int m = 0; m < 2; m++)
#pragma unroll
        for (int n = 0; n < 8; n++)
#pragma unroll
            for (int i = 0; i < 4; i++) c[m][n][i] = 0.0f;

    auto load_chunk = [&](int buf, int kt) {
        char* base = smem + buf * BUF_B;
#pragma unroll
        for (int half = 0; half < 2; half++) {
            int idx = t + half * 256;       // 0..511
            int row = idx >> 2;
            int q   = idx & 3;
            size_t go = (size_t)row * K + kt + q * 8;
            uint32_t so = row * 80 + q * 16;
            cp_async16(base + so,                Agh + go);
            cp_async16(base + TILE_B + so,       Agl + go);
            cp_async16(base + 2 * TILE_B + so,   Bgh + go);
            cp_async16(base + 3 * TILE_B + so,   Bgl + go);
        }
        cp_commit();
    };

    // A-fragment ldmatrix lane offset (bytes): rows m16 tile, k-halves split by sub
    // sub: 0 -> (row+0, k+0), 1 -> (row+8, k+0), 2 -> (row+0, k+8), 3 -> (row+8, k+8)
    const uint32_t aLane = (uint32_t)((warp_m * 32 + (sub & 1) * 8 + rin) * 40
                                      + (sub >> 1) * 8) * 2;
    // B-fragment ldmatrix lane offset: two n8 tiles per x4
    // sub: 0 -> (n+0, k+0), 1 -> (n+0, k+8), 2 -> (n+8, k+0), 3 -> (n+8, k+8)
    const uint32_t bLane = (uint32_t)((warp_n * 64 + (sub >> 1) * 8 + rin) * 40
                                      + (sub & 1) * 8) * 2;

    auto compute_chunk = [&](int buf) {
        const uint32_t base = smem_b + buf * BUF_B;
#pragma unroll
        for (int ks = 0; ks < 2; ks++) {
            const uint32_t kOff = ks * 32;        // 16 elems = 32 bytes
            uint32_t ah[2][4], al[2][4];
#pragma unroll
            for (int m = 0; m < 2; m++) {
                uint32_t ao = base + aLane + (uint32_t)(m * 16 * 80) + kOff;
                ldsm4(ah[m][0], ah[m][1], ah[m][2], ah[m][3], ao);
                ldsm4(al[m][0], al[m][1], al[m][2], al[m][3], ao + TILE_B);
            }
#pragma unroll
            for (int n2 = 0; n2 < 4; n2++) {
                uint32_t bo = base + 2 * TILE_B + bLane + (uint32_t)(n2 * 16 * 80) + kOff;
                uint32_t bh0, bh1, bh2, bh3, bl0, bl1, bl2, bl3;
                ldsm4(bh0, bh1, bh2, bh3, bo);
                ldsm4(bl0, bl1, bl2, bl3, bo + TILE_B);
#pragma unroll
                for (int m = 0; m < 2; m++) {
                    mma_bf16(c[m][n2 * 2],     ah[m], bh0, bh1);   // Ah*Bh
                    mma_bf16(c[m][n2 * 2],     ah[m], bl0, bl1);   // Ah*Bl
                    mma_bf16(c[m][n2 * 2],     al[m], bh0, bh1);   // Al*Bh
                    mma_bf16(c[m][n2 * 2 + 1], ah[m], bh2, bh3);
                    mma_bf16(c[m][n2 * 2 + 1], ah[m], bl2, bl3);
                    mma_bf16(c[m][n2 * 2 + 1], al[m], bh2, bh3);
                }
            }
        }
    };

    const int nc = K / 32;
    load_chunk(0, 0);
    for (int ck = 0; ck < nc; ck++) {
        if (ck + 1 < nc) {
            load_chunk((ck + 1) & 1, (ck + 1) * 32);
            cp_wait1();
        } else {
            cp_wait0();
        }
        __syncthreads();
        compute_chunk(ck & 1);
        __syncthreads();
    }

    // epilogue: bias (+GELU), store fp32 or bf16 hi/lo split
#pragma unroll
    for (int m = 0; m < 2; m++) {
        int r0 = rowBase + warp_m * 32 + m * 16 + g;
#pragma unroll
        for (int n = 0; n < 8; n++) {
            int col = colBase + warp_n * 64 + n * 8 + tg * 2;
            float2 bv = *(const float2*)(bias + col);
            float v0 = c[m][n][0] + bv.x;
            float v1 = c[m][n][1] + bv.y;
            float v2 = c[m][n][2] + bv.x;
            float v3 = c[m][n][3] + bv.y;
            if (ACT == 1) {
                v0 = gelu_exact(v0); v1 = gelu_exact(v1);
                v2 = gelu_exact(v2); v3 = gelu_exact(v3);
            }
            size_t o0 = (size_t)r0 * N + col;
            size_t o1 = (size_t)(r0 + 8) * N + col;
            if (OUTBF) {
                __nv_bfloat16 h0, l0, h1, l1, h2, l2, h3, l3;
                split_bf16(v0, h0, l0); split_bf16(v1, h1, l1);
                split_bf16(v2, h2, l2); split_bf16(v3, h3, l3);
                *(__nv_bfloat162*)(Ch + z * cStrideZ + o0) = __nv_bfloat162(h0, h1);
                *(__nv_bfloat162*)(Cl + z * cStrideZ + o0) = __nv_bfloat162(l0, l1);
                *(__nv_bfloat162*)(Ch + z * cStrideZ + o1) = __nv_bfloat162(h2, h3);
                *(__nv_bfloat162*)(Cl + z * cStrideZ + o1) = __nv_bfloat162(l2, l3);
            } else {
                *(float2*)(C + z * cStrideZ + o0) = make_float2(v0, v1);
                *(float2*)(C + z * cStrideZ + o1) = make_float2(v2, v3);
            }
        }
    }
}

// ---------------- fused attention (z-batched over streams) ----------------
__global__ __launch_bounds__(64) void attn_kernel(
    const float* __restrict__ qkv, const int* __restrict__ mask0,
    const int* __restrict__ mask1, float* __restrict__ outb)
{
    const int z = blockIdx.z;
    const float* __restrict__ qb = qkv + (size_t)z * 3 * MD;
    const float* __restrict__ kb = qb + MD;
    const float* __restrict__ vb = qb + 2 * MD;
    const int* __restrict__ mask = (z == 0) ? mask0 : mask1;
    float* __restrict__ out = outb + (size_t)z * MD;

    const int bh = blockIdx.x;
    const int b = bh / N_HEADS;
    const int h = bh % N_HEADS;
    const int t = threadIdx.x;
    const int q = blockIdx.y * 64 + t;

    __shared__ float Ks[64 * 64];
    __shared__ float Vs[64 * 64];
    __shared__ float mb[SEQ];

#pragma unroll
    for (int j = 0; j < 4; j++) {
        int i = t + j * 64;
        mb[i] = -10000.0f * (1.0f - (float)mask[b * SEQ + i]);
    }

    const size_t qoff = ((size_t)(b * SEQ + q)) * D_MODEL + h * DH;
    float4 q4[16];
    const float4* qp = (const float4*)(qb + qoff);
#pragma unroll
    for (int i = 0; i < 16; i++) q4[i] = qp[i];

    float4 acc[16];
#pragma unroll
    for (int i = 0; i < 16; i++) acc[i] = make_float4(0.f, 0.f, 0.f, 0.f);
    float m = -1e30f, l = 0.0f;

    for (int kc = 0; kc < 4; kc++) {
        __syncthreads();
#pragma unroll
        for (int it = 0; it < 16; it++) {
            int idx = t + it * 64;
            int r = idx >> 4;
            int cc = idx & 15;
            size_t gof = ((size_t)(b * SEQ + kc * 64 + r)) * D_MODEL + h * DH + cc * 4;
            ((float4*)Ks)[idx] = *(const float4*)(kb + gof);
            ((float4*)Vs)[idx] = *(const float4*)(vb + gof);
        }
        __syncthreads();

        for (int kk = 0; kk < 64; kk++) {
            const float4* Kr = (const float4*)(Ks + kk * 64);
            float dot = 0.0f;
#pragma unroll
            for (int i = 0; i < 16; i++) {
                dot += q4[i].x * Kr[i].x + q4[i].y * Kr[i].y
                     + q4[i].z * Kr[i].z + q4[i].w * Kr[i].w;
            }
            float s  = dot * 0.125f + mb[kc * 64 + kk];
            float nm = fmaxf(m, s);
            float corr = __expf(m - nm);
            float p    = __expf(s - nm);
            l = l * corr + p;
            const float4* Vr = (const float4*)(Vs + kk * 64);
#pragma unroll
            for (int i = 0; i < 16; i++) {
                acc[i].x = fmaf(acc[i].x, corr, p * Vr[i].x);
                acc[i].y = fmaf(acc[i].y, corr, p * Vr[i].y);
                acc[i].z = fmaf(acc[i].z, corr, p * Vr[i].z);
                acc[i].w = fmaf(acc[i].w, corr, p * Vr[i].w);
            }
            m = nm;
        }
    }

    float inv = 1.0f / l;
    float4* op = (float4*)(out + qoff);
#pragma unroll
    for (int i = 0; i < 16; i++)
        op[i] = make_float4(acc[i].x * inv, acc[i].y * inv, acc[i].z * inv, acc[i].w * inv);
}

// ---------------- residual add + LayerNorm + bf16 split (2-stream batched) ----------------
__global__ __launch_bounds__(256) void add_ln_kernel(
    float* __restrict__ x0, float* __restrict__ x1, const float* __restrict__ r,
    const float* __restrict__ g0, const float* __restrict__ b0,
    const float* __restrict__ g1, const float* __restrict__ b1,
    __nv_bfloat16* __restrict__ xh0, __nv_bfloat16* __restrict__ xl0,
    __nv_bfloat16* __restrict__ xh1, __nv_bfloat16* __restrict__ xl1,
    int halfRows)
{
    const int row = blockIdx.x;
    const int t = threadIdx.x;
    float* x; const float* g; const float* b;
    __nv_bfloat16 *xh, *xl;
    int lrow;
    if (row < halfRows) { x = x0; g = g0; b = b0; xh = xh0; xl = xl0; lrow = row; }
    else                { x = x1; g = g1; b = b1; xh = xh1; xl = xl1; lrow = row - halfRows; }
    const size_t base  = (size_t)lrow * D_MODEL;
    const size_t rbase = (size_t)row * D_MODEL;

    float v[3];
    float s = 0.f, s2 = 0.f;
#pragma unroll
    for (int j = 0; j < 3; j++) {
        int i = t + j * 256;
        float val = x[base + i] + r[rbase + i];
        v[j] = val;
        s += val;
        s2 += val * val;
    }
    __shared__ float sh1[256], sh2[256];
    sh1[t] = s; sh2[t] = s2;
    __syncthreads();
    for (int o = 128; o > 0; o >>= 1) {
        if (t < o) { sh1[t] += sh1[t + o]; sh2[t] += sh2[t + o]; }
        __syncthreads();
    }
    float mean = sh1[0] * (1.0f / D_MODEL);
    float var  = sh2[0] * (1.0f / D_MODEL) - mean * mean;
    float rstd = rsqrtf(var + 1e-12f);
#pragma unroll
    for (int j = 0; j < 3; j++) {
        int i = t + j * 256;
        float val = (v[j] - mean) * rstd * g[i] + b[i];
        x[base + i] = val;
        __nv_bfloat16 h, l;
        split_bf16(val, h, l);
        xh[base + i] = h;
        xl[base + i] = l;
    }
}

// ---------------- host orchestration ----------------
extern "C" void kernel_launch(void* const* d_in, const int* in_sizes, int n_in,
                              void* d_out, int out_size)
{
    (void)in_sizes; (void)n_in; (void)out_size;
    const float* in_x    = (const float*)d_in[0];
    const float* in_y    = (const float*)d_in[1];
    const int*   x_mask  = (const int*)d_in[2];
    const int*   y_mask  = (const int*)d_in[3];
    const float* ax_w = (const float*)d_in[4];
    const float* ax_b = (const float*)d_in[5];
    const float* cx_w = (const float*)d_in[6];
    const float* cx_b = (const float*)d_in[7];
    const float* fx_w1 = (const float*)d_in[8];
    const float* fx_b1 = (const float*)d_in[9];
    const float* fx_w2 = (const float*)d_in[10];
    const float* fx_b2 = (const float*)d_in[11];
    const float* ay_w = (const float*)d_in[12];
    const float* ay_b = (const float*)d_in[13];
    const float* cy_w = (const float*)d_in[14];
    const float* cy_b = (const float*)d_in[15];
    const float* fy_w1 = (const float*)d_in[16];
    const float* fy_b1 = (const float*)d_in[17];
    const float* fy_w2 = (const float*)d_in[18];
    const float* fy_b2 = (const float*)d_in[19];
    const float* lnx_g = (const float*)d_in[20];
    const float* lnx_b = (const float*)d_in[21];
    const float* lny_g = (const float*)d_in[22];
    const float* lny_b = (const float*)d_in[23];
    float* out = (float*)d_out;

    float *gx, *gy, *gqkv, *gtmp;
    __nv_bfloat16 *gxh, *gxl, *gyh, *gyl, *ghh, *ghl, *gwth, *gwtl;
    cudaGetSymbolAddress((void**)&gx,   g_x);
    cudaGetSymbolAddress((void**)&gy,   g_y);
    cudaGetSymbolAddress((void**)&gqkv, g_qkv);
    cudaGetSymbolAddress((void**)&gtmp, g_tmp);
    cudaGetSymbolAddress((void**)&gxh,  g_xh);
    cudaGetSymbolAddress((void**)&gxl,  g_xl);
    cudaGetSymbolAddress((void**)&gyh,  g_yh);
    cudaGetSymbolAddress((void**)&gyl,  g_yl);
    cudaGetSymbolAddress((void**)&ghh,  g_hh);
    cudaGetSymbolAddress((void**)&ghl,  g_hl);
    cudaGetSymbolAddress((void**)&gwth, g_wth);
    cudaGetSymbolAddress((void**)&gwtl, g_wtl);

    cudaFuncSetAttribute(mma_gemm<0,0>, cudaFuncAttributeMaxDynamicSharedMemorySize, SMEM_BYTES);
    cudaFuncSetAttribute(mma_gemm<1,1>, cudaFuncAttributeMaxDynamicSharedMemorySize, SMEM_BYTES);

    cudaMemcpyAsync(gx, in_x, MD * sizeof(float), cudaMemcpyDeviceToDevice, 0);
    cudaMemcpyAsync(gy, in_y, MD * sizeof(float), cudaMemcpyDeviceToDevice, 0);

    // weight transpose + bf16 split (3 batched launches)
    const dim3 wblk(32, 8);
    wconv4_kernel<<<dim3(24, 24, 72), wblk>>>(ax_w, cx_w, ay_w, cy_w,
                                              gwth + OFF_AX, gwtl + OFF_AX, 768, 768, 18);
    wconv4_kernel<<<dim3(96, 24, 12), wblk>>>(fx_w1, fy_w1, fx_w1, fy_w1,
                                              gwth + OFF_FXW1, gwtl + OFF_FXW1, 768, 3072, 6);
    wconv4_kernel<<<dim3(24, 96, 12), wblk>>>(fx_w2, fy_w2, fx_w2, fy_w2,
                                              gwth + OFF_FXW2, gwtl + OFF_FXW2, 3072, 768, 6);

    // initial activation split (both streams)
    aconv2_kernel<<<(int)(2 * MD / 256), 256>>>(gx, gy, gxh, gxl, gyh, gyl);

    const dim3 gridSelf(6, 16, 6);
    const dim3 gridCross(6, 16, 3);
    const dim3 gridF1(24, 16, 2);
    const dim3 gridF2(6, 16, 2);

    for (int L = 0; L < NLAYER; L++) {
        const size_t pOff  = (size_t)L * 3 * DDW;
        const size_t bOff  = (size_t)L * 3 * D_MODEL;
        const size_t w1Off = (size_t)L * D_MODEL * DFF;
        const size_t w2Off = (size_t)L * DFF * D_MODEL;

        // ---- 1+2) batched self-attention (x and y) ----
        mma_gemm<0,0><<<gridSelf, 256, SMEM_BYTES>>>(
            gxh, gxl, gyh, gyl, 3,
            gwth + OFF_AX + pOff, gwtl + OFF_AX + pOff,
            gwth + OFF_AY + pOff, gwtl + OFF_AY + pOff, 3,
            ax_b + bOff, ay_b + bOff,
            gqkv, nullptr, nullptr, D_MODEL, D_MODEL, (size_t)DDW, D_MODEL, MD);
        attn_kernel<<<dim3(BATCH * N_HEADS, 4, 2), 64>>>(gqkv, x_mask, y_mask, gtmp);
        add_ln_kernel<<<2 * MROWS, 256>>>(gx, gy, gtmp,
            lnx_g, lnx_b, lny_g, lny_b, gxh, gxl, gyh, gyl, MROWS);

        // ---- 3) x cross-attention (q from x, kv from updated y) ----
        mma_gemm<0,0><<<gridCross, 256, SMEM_BYTES>>>(
            gxh, gxl, gyh, gyl, 1,
            gwth + OFF_CX + pOff, gwtl + OFF_CX + pOff,
            gwth + OFF_CX + pOff, gwtl + OFF_CX + pOff, 8,
            cx_b + bOff, cx_b + bOff,
            gqkv, nullptr, nullptr, D_MODEL, D_MODEL, (size_t)DDW, D_MODEL, MD);
        attn_kernel<<<dim3(BATCH * N_HEADS, 4, 1), 64>>>(gqkv, y_mask, y_mask, gtmp);
        add_ln_kernel<<<MROWS, 256>>>(gx, gx, gtmp,
            lnx_g + D_MODEL, lnx_b + D_MODEL, lnx_g + D_MODEL, lnx_b + D_MODEL,
            gxh, gxl, gxh, gxl, MROWS);

        // ---- 4) y cross-attention (q from y, kv from updated x) ----
        mma_gemm<0,0><<<gridCross, 256, SMEM_BYTES>>>(
            gyh, gyl, gxh, gxl, 1,
            gwth + OFF_CY + pOff, gwtl + OFF_CY + pOff,
            gwth + OFF_CY + pOff, gwtl + OFF_CY + pOff, 8,
            cy_b + bOff, cy_b + bOff,
            gqkv, nullptr, nullptr, D_MODEL, D_MODEL, (size_t)DDW, D_MODEL, MD);
        attn_kernel<<<dim3(BATCH * N_HEADS, 4, 1), 64>>>(gqkv, x_mask, x_mask, gtmp);
        add_ln_kernel<<<MROWS, 256>>>(gy, gy, gtmp,
            lny_g + D_MODEL, lny_b + D_MODEL, lny_g + D_MODEL, lny_b + D_MODEL,
            gyh, gyl, gyh, gyl, MROWS);

        // ---- 5+6) batched FFN (x and y) ----
        mma_gemm<1,1><<<gridF1, 256, SMEM_BYTES>>>(
            gxh, gxl, gyh, gyl, 1,
            gwth + OFF_FXW1 + w1Off, gwtl + OFF_FXW1 + w1Off,
            gwth + OFF_FYW1 + w1Off, gwtl + OFF_FYW1 + w1Off, 1,
            fx_b1 + (size_t)L * DFF, fy_b1 + (size_t)L * DFF,
            nullptr, ghh, ghl, DFF, D_MODEL, 0, 0, HD);
        mma_gemm<0,0><<<gridF2, 256, SMEM_BYTES>>>(
            ghh, ghl, ghh + HD, ghl + HD, 1,
            gwth + OFF_FXW2 + w2Off, gwtl + OFF_FXW2 + w2Off,
            gwth + OFF_FYW2 + w2Off, gwtl + OFF_FYW2 + w2Off, 1,
            fx_b2 + (size_t)L * D_MODEL, fy_b2 + (size_t)L * D_MODEL,
            gtmp, nullptr, nullptr, D_MODEL, DFF, 0, 0, MD);
        add_ln_kernel<<<2 * MROWS, 256>>>(gx, gy, gtmp,
            lnx_g + 2 * D_MODEL, lnx_b + 2 * D_MODEL,
            lny_g + 2 * D_MODEL, lny_b + 2 * D_MODEL,
            gxh, gxl, gyh, gyl, MROWS);
    }

    cudaMemcpyAsync(out,      gx, MD * sizeof(float), cudaMemcpyDeviceToDevice, 0);
    cudaMemcpyAsync(out + MD, gy, MD * sizeof(float), cudaMemcpyDeviceToDevice, 0);
}